// round 1
// baseline (speedup 1.0000x reference)
#include <cuda_runtime.h>
#include <math.h>

#define BATCH 2
#define SEQ   2048
#define HID   1024
#define NH    16
#define HD    64
#define MTOT  (BATCH*SEQ)           /* 4096 rows for the projections */
#define OUT_ELEMS   (MTOT*HID)      /* 4,194,304 */
#define W_ELEMS     (BATCH*NH*SEQ*SEQ) /* 134,217,728 */

/* ---------------- scratch (no allocations allowed) ---------------- */
__device__ float g_Q[BATCH*NH*SEQ*HD];
__device__ float g_K[BATCH*NH*SEQ*HD];
__device__ float g_V[BATCH*NH*SEQ*HD];
__device__ float g_attn[BATCH*SEQ*HID];
__device__ float g_cos[SEQ*(HD/2)];
__device__ float g_sin[SEQ*(HD/2)];

/* ---------------- RoPE tables (double precision for accuracy) ----- */
__global__ void rope_table_kernel() {
    int idx = blockIdx.x * blockDim.x + threadIdx.x;
    if (idx >= SEQ * (HD/2)) return;
    int s = idx >> 5;           /* HD/2 == 32 */
    int j = idx & 31;
    double inv = exp(-((double)(2*j) / (double)HD) * log(10000.0));
    double ang = (double)s * inv;
    g_cos[idx] = (float)cos(ang);
    g_sin[idx] = (float)sin(ang);
}

/* ---------------- shared 128x128x16 fp32 GEMM core ----------------
   C[m,n] = sum_k A[m,k] * W[n,k]   (A: 4096x1024 rm, W: 1024x1024 rm)
   256 threads, each computes an 8x8 (2x2 blocks of 4x4).               */
#define GS 132   /* padded smem row stride (floats) */

__device__ __forceinline__ void gemm_tile(const float* __restrict__ A,
                                          const float* __restrict__ W,
                                          float acc[8][8],
                                          float* As, float* Bs)
{
    const int tid = threadIdx.x;
    const int tx = tid & 15, ty = tid >> 4;
    const int m0 = blockIdx.y * 128;
    const int n0 = blockIdx.x * 128;

    for (int k0 = 0; k0 < 1024; k0 += 16) {
        if (k0) __syncthreads();
#pragma unroll
        for (int i = 0; i < 2; i++) {
            int f   = i * 256 + tid;       /* 0..511 */
            int row = f >> 2;
            int kq  = (f & 3) << 2;
            float4 av = *(const float4*)(A + (long)(m0 + row) * 1024 + k0 + kq);
            As[(kq+0)*GS + row] = av.x;
            As[(kq+1)*GS + row] = av.y;
            As[(kq+2)*GS + row] = av.z;
            As[(kq+3)*GS + row] = av.w;
            float4 bv = *(const float4*)(W + (long)(n0 + row) * 1024 + k0 + kq);
            Bs[(kq+0)*GS + row] = bv.x;
            Bs[(kq+1)*GS + row] = bv.y;
            Bs[(kq+2)*GS + row] = bv.z;
            Bs[(kq+3)*GS + row] = bv.w;
        }
        __syncthreads();
#pragma unroll
        for (int kk = 0; kk < 16; kk++) {
            float4 a0 = *(const float4*)(As + kk*GS + ty*4);
            float4 a1 = *(const float4*)(As + kk*GS + 64 + ty*4);
            float4 b0 = *(const float4*)(Bs + kk*GS + tx*4);
            float4 b1 = *(const float4*)(Bs + kk*GS + 64 + tx*4);
            float a[8] = {a0.x,a0.y,a0.z,a0.w,a1.x,a1.y,a1.z,a1.w};
            float b[8] = {b0.x,b0.y,b0.z,b0.w,b1.x,b1.y,b1.z,b1.w};
#pragma unroll
            for (int ii = 0; ii < 8; ii++)
#pragma unroll
                for (int jj = 0; jj < 8; jj++)
                    acc[ii][jj] = fmaf(a[ii], b[jj], acc[ii][jj]);
        }
    }
    __syncthreads();
}

/* ---- fused QKV projection + bias + RoPE, output layout (B,H,S,D) ---- */
__global__ void __launch_bounds__(256)
qkv_kernel(const float* __restrict__ qin, const float* __restrict__ kin,
           const float* __restrict__ vin,
           const float* __restrict__ Wq, const float* __restrict__ Wk,
           const float* __restrict__ Wv,
           const float* __restrict__ bq, const float* __restrict__ bk,
           const float* __restrict__ bv)
{
    __shared__ float As[16*GS];
    __shared__ float Bs[16*GS];

    const int z = blockIdx.z;
    const float* A    = (z == 0) ? qin : (z == 1) ? kin : vin;
    const float* W    = (z == 0) ? Wq  : (z == 1) ? Wk  : Wv;
    const float* bias = (z == 0) ? bq  : (z == 1) ? bk  : bv;
    float* dst        = (z == 0) ? g_Q : (z == 1) ? g_K : g_V;

    float acc[8][8];
#pragma unroll
    for (int i = 0; i < 8; i++)
#pragma unroll
        for (int j = 0; j < 8; j++) acc[i][j] = 0.f;

    gemm_tile(A, W, acc, As, Bs);

    const int tx = threadIdx.x & 15, ty = threadIdx.x >> 4;
    const int m0 = blockIdx.y * 128, n0 = blockIdx.x * 128;

#pragma unroll
    for (int ih = 0; ih < 2; ih++) {
#pragma unroll
        for (int i = 0; i < 4; i++) {
            int m = m0 + ih*64 + ty*4 + i;
            int bb = m >> 11;        /* SEQ = 2048 */
            int s  = m & 2047;
#pragma unroll
            for (int jh = 0; jh < 2; jh++) {
                int cb = n0 + jh*64 + tx*4;
#pragma unroll
                for (int p = 0; p < 2; p++) {
                    int c  = cb + p*2;
                    float v0 = acc[ih*4+i][jh*4+p*2]   + bias[c];
                    float v1 = acc[ih*4+i][jh*4+p*2+1] + bias[c+1];
                    int hh = c >> 6, d = c & 63;
                    long o = ((long)(bb*NH + hh) * SEQ + s) * HD + d;
                    if (z < 2) {
                        float cs = g_cos[s*32 + (d >> 1)];
                        float sn = g_sin[s*32 + (d >> 1)];
                        dst[o]   = v0*cs - v1*sn;
                        dst[o+1] = v0*sn + v1*cs;
                    } else {
                        dst[o]   = v0;
                        dst[o+1] = v1;
                    }
                }
            }
        }
    }
}

/* ---- output projection: g_attn(4096x1024) @ Wo^T + bo -> d_out ---- */
__global__ void __launch_bounds__(256)
outproj_kernel(const float* __restrict__ Wo, const float* __restrict__ bo,
               float* __restrict__ out)
{
    __shared__ float As[16*GS];
    __shared__ float Bs[16*GS];

    float acc[8][8];
#pragma unroll
    for (int i = 0; i < 8; i++)
#pragma unroll
        for (int j = 0; j < 8; j++) acc[i][j] = 0.f;

    gemm_tile(g_attn, Wo, acc, As, Bs);

    const int tx = threadIdx.x & 15, ty = threadIdx.x >> 4;
    const int m0 = blockIdx.y * 128, n0 = blockIdx.x * 128;

#pragma unroll
    for (int ih = 0; ih < 2; ih++)
#pragma unroll
        for (int i = 0; i < 4; i++) {
            int m = m0 + ih*64 + ty*4 + i;
#pragma unroll
            for (int jh = 0; jh < 2; jh++) {
#pragma unroll
                for (int j = 0; j < 4; j++) {
                    int c = n0 + jh*64 + tx*4 + j;
                    out[(long)m * HID + c] = acc[ih*4+i][jh*4+j] + bo[c];
                }
            }
        }
}

/* ---------------- attention ----------------
   One block per (q-tile of 64 rows, head, batch). 256 threads (16x16),
   each owns a 4x4 of every 64x64 tile. Two passes over K:
     pass 1: exact online row max + sum (registers only)
     pass 2: recompute scores -> normalized weights -> gmem write + O += W*V
   Upper-triangle k-tiles zero-filled (d_out is poisoned).              */
#define TS 68    /* padded transpose stride */

__global__ void __launch_bounds__(256)
attn_kernel(float* __restrict__ wout, int write_w)
{
    extern __shared__ float sm[];
    float* Qt = sm;                /* [64][TS] Q transposed: Qt[d][r]  */
    float* Kt = Qt + 64*TS;        /* [64][TS] K transposed: Kt[d][c]  */
    float* Wt = Kt + 64*TS;        /* [64][TS] W transposed: Wt[c][r]  */
    float* Vs = Wt + 64*TS;        /* [64][64] V row-major             */

    const int tid = threadIdx.x;
    const int tx = tid & 15, ty = tid >> 4;
    const int qt = blockIdx.x, h = blockIdx.y, b = blockIdx.z;
    const int q0 = qt * 64;
    const long basebh = (long)(b*NH + h) * SEQ;
    const float scale = 0.125f;    /* 1/sqrt(64) */

    /* load Q tile, transposed */
    {
        const float* Qg = g_Q + (basebh + q0) * HD;
        for (int f = tid; f < 1024; f += 256) {
            int r = f >> 4, dc = (f & 15) << 2;
            float4 v = *(const float4*)(Qg + r*HD + dc);
            Qt[(dc+0)*TS + r] = v.x;
            Qt[(dc+1)*TS + r] = v.y;
            Qt[(dc+2)*TS + r] = v.z;
            Qt[(dc+3)*TS + r] = v.w;
        }
    }
    __syncthreads();

    float mreg[4], lreg[4];
#pragma unroll
    for (int i = 0; i < 4; i++) { mreg[i] = -1e30f; lreg[i] = 0.f; }

    /* ---------------- PASS 1: row max & sum ---------------- */
    for (int kb = 0; kb <= qt; kb++) {
        const float* Kg = g_K + (basebh + kb*64) * HD;
        for (int f = tid; f < 1024; f += 256) {
            int r = f >> 4, dc = (f & 15) << 2;
            float4 v = *(const float4*)(Kg + r*HD + dc);
            Kt[(dc+0)*TS + r] = v.x;
            Kt[(dc+1)*TS + r] = v.y;
            Kt[(dc+2)*TS + r] = v.z;
            Kt[(dc+3)*TS + r] = v.w;
        }
        __syncthreads();

        float s[4][4];
#pragma unroll
        for (int i = 0; i < 4; i++)
#pragma unroll
            for (int j = 0; j < 4; j++) s[i][j] = 0.f;
#pragma unroll 16
        for (int d = 0; d < 64; d++) {
            float4 qa = *(const float4*)(Qt + d*TS + ty*4);
            float4 kv = *(const float4*)(Kt + d*TS + tx*4);
            float a[4] = {qa.x,qa.y,qa.z,qa.w};
            float c[4] = {kv.x,kv.y,kv.z,kv.w};
#pragma unroll
            for (int i = 0; i < 4; i++)
#pragma unroll
                for (int j = 0; j < 4; j++) s[i][j] = fmaf(a[i], c[j], s[i][j]);
        }
        int k0 = kb * 64;
#pragma unroll
        for (int i = 0; i < 4; i++) {
            int q = q0 + ty*4 + i;
#pragma unroll
            for (int j = 0; j < 4; j++) {
                int k = k0 + tx*4 + j;
                s[i][j] = (k <= q) ? s[i][j] * scale : -1e30f;
            }
            float tm = fmaxf(fmaxf(s[i][0], s[i][1]), fmaxf(s[i][2], s[i][3]));
#pragma unroll
            for (int off = 1; off < 16; off <<= 1)
                tm = fmaxf(tm, __shfl_xor_sync(0xffffffffu, tm, off));
            float mn = fmaxf(mreg[i], tm);
            float ps = expf(s[i][0]-mn) + expf(s[i][1]-mn)
                     + expf(s[i][2]-mn) + expf(s[i][3]-mn);
#pragma unroll
            for (int off = 1; off < 16; off <<= 1)
                ps += __shfl_xor_sync(0xffffffffu, ps, off);
            lreg[i] = lreg[i] * expf(mreg[i] - mn) + ps;
            mreg[i] = mn;
        }
        __syncthreads();
    }

    float inv_l[4];
#pragma unroll
    for (int i = 0; i < 4; i++) inv_l[i] = 1.f / lreg[i];

    float o[4][4];
#pragma unroll
    for (int i = 0; i < 4; i++)
#pragma unroll
        for (int j = 0; j < 4; j++) o[i][j] = 0.f;

    /* ---------------- PASS 2: weights + O ---------------- */
    for (int kb = 0; kb <= qt; kb++) {
        const float* Kg = g_K + (basebh + kb*64) * HD;
        const float* Vg = g_V + (basebh + kb*64) * HD;
        for (int f = tid; f < 1024; f += 256) {
            int r = f >> 4, dc = (f & 15) << 2;
            float4 v = *(const float4*)(Kg + r*HD + dc);
            Kt[(dc+0)*TS + r] = v.x;
            Kt[(dc+1)*TS + r] = v.y;
            Kt[(dc+2)*TS + r] = v.z;
            Kt[(dc+3)*TS + r] = v.w;
            *(float4*)(Vs + r*64 + dc) = *(const float4*)(Vg + r*HD + dc);
        }
        __syncthreads();

        float s[4][4];
#pragma unroll
        for (int i = 0; i < 4; i++)
#pragma unroll
            for (int j = 0; j < 4; j++) s[i][j] = 0.f;
#pragma unroll 16
        for (int d = 0; d < 64; d++) {
            float4 qa = *(const float4*)(Qt + d*TS + ty*4);
            float4 kv = *(const float4*)(Kt + d*TS + tx*4);
            float a[4] = {qa.x,qa.y,qa.z,qa.w};
            float c[4] = {kv.x,kv.y,kv.z,kv.w};
#pragma unroll
            for (int i = 0; i < 4; i++)
#pragma unroll
                for (int j = 0; j < 4; j++) s[i][j] = fmaf(a[i], c[j], s[i][j]);
        }
        int k0 = kb * 64;
        float w[4][4];
#pragma unroll
        for (int i = 0; i < 4; i++) {
            int q = q0 + ty*4 + i;
#pragma unroll
            for (int j = 0; j < 4; j++) {
                int k = k0 + tx*4 + j;
                w[i][j] = (k <= q) ? expf(s[i][j]*scale - mreg[i]) * inv_l[i] : 0.f;
            }
        }
        if (write_w) {
#pragma unroll
            for (int i = 0; i < 4; i++) {
                long addr = (basebh + q0 + ty*4 + i) * (long)SEQ + k0 + tx*4;
                float4 w4 = make_float4(w[i][0], w[i][1], w[i][2], w[i][3]);
                *(float4*)(wout + addr) = w4;
            }
        }
#pragma unroll
        for (int i = 0; i < 4; i++)
#pragma unroll
            for (int j = 0; j < 4; j++)
                Wt[(tx*4+j)*TS + ty*4 + i] = w[i][j];
        __syncthreads();

#pragma unroll 16
        for (int c = 0; c < 64; c++) {
            float4 wa = *(const float4*)(Wt + c*TS + ty*4);
            float4 vv = *(const float4*)(Vs + c*64 + tx*4);
            float a[4] = {wa.x,wa.y,wa.z,wa.w};
            float v2[4] = {vv.x,vv.y,vv.z,vv.w};
#pragma unroll
            for (int i = 0; i < 4; i++)
#pragma unroll
                for (int j = 0; j < 4; j++) o[i][j] = fmaf(a[i], v2[j], o[i][j]);
        }
        __syncthreads();
    }

    /* zero-fill the masked (upper-triangle) k-tiles */
    if (write_w) {
        float4 z4 = make_float4(0.f, 0.f, 0.f, 0.f);
        for (int kb = qt + 1; kb < SEQ/64; kb++) {
            for (int f = tid; f < 1024; f += 256) {
                int r = f >> 4, cc = (f & 15) << 2;
                *(float4*)(wout + (basebh + q0 + r) * (long)SEQ + kb*64 + cc) = z4;
            }
        }
    }

    /* write O into (B, S, HID) scratch for the output projection */
#pragma unroll
    for (int i = 0; i < 4; i++) {
        long addr = ((long)(b*SEQ + q0 + ty*4 + i)) * HID + h*HD + tx*4;
        float4 o4 = make_float4(o[i][0], o[i][1], o[i][2], o[i][3]);
        *(float4*)(g_attn + addr) = o4;
    }
}

/* ---------------- launcher ---------------- */
extern "C" void kernel_launch(void* const* d_in, const int* in_sizes, int n_in,
                              void* d_out, int out_size)
{
    const float* q  = (const float*)d_in[0];
    const float* k  = (const float*)d_in[1];
    const float* v  = (const float*)d_in[2];
    const float* Wq = (const float*)d_in[3];
    const float* bq = (const float*)d_in[4];
    const float* Wk = (const float*)d_in[5];
    const float* bk = (const float*)d_in[6];
    const float* Wv = (const float*)d_in[7];
    const float* bv = (const float*)d_in[8];
    const float* Wo = (const float*)d_in[9];
    const float* bo = (const float*)d_in[10];

    float* out  = (float*)d_out;
    int write_w = (out_size >= OUT_ELEMS + W_ELEMS) ? 1 : 0;
    float* wout = out + OUT_ELEMS;

    rope_table_kernel<<<(SEQ*32 + 255)/256, 256>>>();
    qkv_kernel<<<dim3(8, 32, 3), 256>>>(q, k, v, Wq, Wk, Wv, bq, bk, bv);

    size_t smem = (size_t)(3*64*TS + 64*64) * sizeof(float);  /* ~67 KB */
    cudaFuncSetAttribute(attn_kernel,
                         cudaFuncAttributeMaxDynamicSharedMemorySize, (int)smem);
    attn_kernel<<<dim3(SEQ/64, NH, BATCH), 256, smem>>>(wout, write_w);

    outproj_kernel<<<dim3(8, 32), 256>>>(Wo, bo, out);
}

// round 3
// speedup vs baseline: 1.2369x; 1.2369x over previous
#include <cuda_runtime.h>
#include <cuda_bf16.h>
#include <math.h>
#include <stdint.h>

#define BATCH 2
#define SEQ   2048
#define HID   1024
#define NH    16
#define HD    64
#define MTOT  (BATCH*SEQ)
#define OUT_ELEMS   (MTOT*HID)
#define W_ELEMS     (BATCH*NH*SEQ*SEQ)
#define KS3   3072               /* split-K: [hi | lo | hi] x 1024 */

/* ---------------- scratch (no allocations allowed) ---------------- */
__device__ float g_Q[BATCH*NH*SEQ*HD];
__device__ float g_K[BATCH*NH*SEQ*HD];
__device__ float g_V[BATCH*NH*SEQ*HD];
__device__ float g_attn[BATCH*SEQ*HID];
__device__ float g_cos[SEQ*(HD/2)];
__device__ float g_sin[SEQ*(HD/2)];

/* bf16 split operands (A-format: [ah|al|ah], B-format: [bh|bh|bl]) */
__device__ __nv_bfloat16 s_q [MTOT*KS3];
__device__ __nv_bfloat16 s_k [MTOT*KS3];
__device__ __nv_bfloat16 s_v [MTOT*KS3];
__device__ __nv_bfloat16 s_at[MTOT*KS3];
__device__ __nv_bfloat16 s_wq[HID*KS3];
__device__ __nv_bfloat16 s_wk[HID*KS3];
__device__ __nv_bfloat16 s_wv[HID*KS3];
__device__ __nv_bfloat16 s_wo[HID*KS3];

/* ---------------- mma.sync / ldmatrix helpers ---------------- */
__device__ __forceinline__ uint32_t smem_u32(const void* p) {
    uint32_t a;
    asm("{ .reg .u64 t; cvta.to.shared.u64 t, %1; cvt.u32.u64 %0, t; }"
        : "=r"(a) : "l"(p));
    return a;
}
__device__ __forceinline__ void ldsm4(uint32_t& r0, uint32_t& r1,
                                      uint32_t& r2, uint32_t& r3, uint32_t addr)
{
    asm volatile("ldmatrix.sync.aligned.m8n8.x4.shared.b16 {%0,%1,%2,%3}, [%4];"
                 : "=r"(r0), "=r"(r1), "=r"(r2), "=r"(r3) : "r"(addr));
}
__device__ __forceinline__ void mma_bf16(float* d, const uint32_t* a,
                                         uint32_t b0, uint32_t b1)
{
    asm volatile(
        "mma.sync.aligned.m16n8k16.row.col.f32.bf16.bf16.f32 "
        "{%0,%1,%2,%3}, {%4,%5,%6,%7}, {%8,%9}, {%0,%1,%2,%3};"
        : "+f"(d[0]), "+f"(d[1]), "+f"(d[2]), "+f"(d[3])
        : "r"(a[0]), "r"(a[1]), "r"(a[2]), "r"(a[3]), "r"(b0), "r"(b1));
}

/* ---------------- RoPE tables (double precision) ----------------- */
__global__ void rope_table_kernel() {
    int idx = blockIdx.x * blockDim.x + threadIdx.x;
    if (idx >= SEQ * (HD/2)) return;
    int s = idx >> 5;
    int j = idx & 31;
    double inv = exp(-((double)(2*j) / (double)HD) * log(10000.0));
    double ang = (double)s * inv;
    g_cos[idx] = (float)cos(ang);
    g_sin[idx] = (float)sin(ang);
}

/* -------- fp32 -> bf16 split, A-format: [hi | lo | hi] ----------- */
__global__ void __launch_bounds__(256)
split_a_kernel(const float* __restrict__ src, __nv_bfloat16* __restrict__ dst, int n)
{
    int idx = blockIdx.x * blockDim.x + threadIdx.x;
    if (idx >= n) return;
    float x = src[idx];
    int row = idx >> 10, kk = idx & 1023;
    int blk = kk >> 5,  j  = kk & 31;
    __nv_bfloat16 hi = __float2bfloat16(x);
    __nv_bfloat16 lo = __float2bfloat16(x - __bfloat162float(hi));
    size_t base = (size_t)row * KS3 + blk*96 + j;
    dst[base]      = hi;
    dst[base + 32] = lo;
    dst[base + 64] = hi;
}
/* -------- fp32 -> bf16 split, B-format: [hi | hi | lo] ----------- */
__global__ void __launch_bounds__(256)
split_b_kernel(const float* __restrict__ src, __nv_bfloat16* __restrict__ dst, int n)
{
    int idx = blockIdx.x * blockDim.x + threadIdx.x;
    if (idx >= n) return;
    float x = src[idx];
    int row = idx >> 10, kk = idx & 1023;
    int blk = kk >> 5,  j  = kk & 31;
    __nv_bfloat16 hi = __float2bfloat16(x);
    __nv_bfloat16 lo = __float2bfloat16(x - __bfloat162float(hi));
    size_t base = (size_t)row * KS3 + blk*96 + j;
    dst[base]      = hi;
    dst[base + 32] = hi;
    dst[base + 64] = lo;
}

/* ================= mma.sync bf16 GEMM =================
   C[m,n] = sum_{k<3072} A[m,k] * B[n,k]  (fp32-via-split).
   CTA tile 128x128, 256 threads = 8 warps (4x2), warp tile 32x64.
   mode 0: +bias, RoPE, write (B,H,S,D)
   mode 1: +bias,       write (B,H,S,D)
   mode 2: +bias,       write row-major [M x 1024]                    */
#define SSTR 72                       /* smem row stride in bf16 */

__global__ void __launch_bounds__(256)
gemm_mma(const __nv_bfloat16* __restrict__ A,
         const __nv_bfloat16* __restrict__ B,
         const float* __restrict__ bias,
         float* __restrict__ dst, int mode)
{
    __shared__ __align__(16) __nv_bfloat16 As[128*SSTR];
    __shared__ __align__(16) __nv_bfloat16 Bs[128*SSTR];

    const int tid = threadIdx.x;
    const int wid = tid >> 5, l = tid & 31;
    const int warp_m = wid >> 1, warp_n = wid & 1;
    const int m0 = blockIdx.y * 128;
    const int n0 = blockIdx.x * 128;

    const uint32_t asb = smem_u32(As);
    const uint32_t bsb = smem_u32(Bs);

    const uint4* gA = (const uint4*)(A + (size_t)m0 * KS3);
    const uint4* gB = (const uint4*)(B + (size_t)n0 * KS3);

    float acc[2][8][4];
#pragma unroll
    for (int i = 0; i < 2; i++)
#pragma unroll
        for (int j = 0; j < 8; j++)
#pragma unroll
            for (int p = 0; p < 4; p++) acc[i][j][p] = 0.f;

    /* precomputed ldmatrix smem addresses (bytes) */
    uint32_t a_addr[2], b_addr[4];
#pragma unroll
    for (int mt = 0; mt < 2; mt++) {
        int row = warp_m*32 + mt*16 + (l & 15);
        int col = (l >> 4) * 8;
        a_addr[mt] = asb + (row*SSTR + col) * 2;
    }
#pragma unroll
    for (int nt = 0; nt < 4; nt++) {
        int row = warp_n*64 + nt*16 + (l & 7) + ((l >> 4) & 1) * 8;
        int col = ((l >> 3) & 1) * 8;
        b_addr[nt] = bsb + (row*SSTR + col) * 2;
    }

    for (int it = 0; it < KS3/64; it++) {          /* 48 iters, 64 bf16 each */
        if (it) __syncthreads();
#pragma unroll
        for (int u = 0; u < 4; u++) {
            int f = u * 256 + tid;                 /* 0..1023 */
            int r = f >> 3, c = f & 7;
            ((uint4*)As)[r*(SSTR/8) + c] = gA[(size_t)r*(KS3/8) + it*8 + c];
            ((uint4*)Bs)[r*(SSTR/8) + c] = gB[(size_t)r*(KS3/8) + it*8 + c];
        }
        __syncthreads();

#pragma unroll
        for (int ks = 0; ks < 4; ks++) {           /* 4 x k16 */
            uint32_t a[2][4], b[4][4];
#pragma unroll
            for (int mt = 0; mt < 2; mt++)
                ldsm4(a[mt][0], a[mt][1], a[mt][2], a[mt][3],
                      a_addr[mt] + ks*32);
#pragma unroll
            for (int nt = 0; nt < 4; nt++)
                ldsm4(b[nt][0], b[nt][1], b[nt][2], b[nt][3],
                      b_addr[nt] + ks*32);
#pragma unroll
            for (int mt = 0; mt < 2; mt++)
#pragma unroll
                for (int nt = 0; nt < 4; nt++) {
                    mma_bf16(acc[mt][nt*2],   a[mt], b[nt][0], b[nt][1]);
                    mma_bf16(acc[mt][nt*2+1], a[mt], b[nt][2], b[nt][3]);
                }
        }
    }

    /* ---------------- epilogue ---------------- */
    const int g = l >> 2, q = l & 3;
#pragma unroll
    for (int mt = 0; mt < 2; mt++) {
        int mrow0 = m0 + warp_m*32 + mt*16 + g;    /* rows mrow0, mrow0+8 */
#pragma unroll
        for (int nt2 = 0; nt2 < 8; nt2++) {
            int ncol = n0 + warp_n*64 + nt2*8 + q*2;
            float b0 = bias[ncol], b1 = bias[ncol+1];
            float c0 = acc[mt][nt2][0] + b0;
            float c1 = acc[mt][nt2][1] + b1;
            float c2 = acc[mt][nt2][2] + b0;
            float c3 = acc[mt][nt2][3] + b1;

            if (mode == 2) {
                *(float2*)(dst + (size_t)mrow0    *HID + ncol) = make_float2(c0, c1);
                *(float2*)(dst + (size_t)(mrow0+8)*HID + ncol) = make_float2(c2, c3);
            } else {
                int h = ncol >> 6, d = ncol & 63;
                int bb0 = mrow0 >> 11, ss0 = mrow0 & 2047;
                int mrow1 = mrow0 + 8;
                int bb1 = mrow1 >> 11, ss1 = mrow1 & 2047;
                if (mode == 0) {
                    float cs0 = g_cos[ss0*32 + (d>>1)], sn0 = g_sin[ss0*32 + (d>>1)];
                    float cs1 = g_cos[ss1*32 + (d>>1)], sn1 = g_sin[ss1*32 + (d>>1)];
                    float t0 = c0*cs0 - c1*sn0, t1 = c0*sn0 + c1*cs0;
                    float t2 = c2*cs1 - c3*sn1, t3 = c2*sn1 + c3*cs1;
                    c0 = t0; c1 = t1; c2 = t2; c3 = t3;
                }
                *(float2*)(dst + (((size_t)(bb0*NH + h)*SEQ + ss0) << 6) + d)
                    = make_float2(c0, c1);
                *(float2*)(dst + (((size_t)(bb1*NH + h)*SEQ + ss1) << 6) + d)
                    = make_float2(c2, c3);
            }
        }
    }
}

/* ---------------- attention (fp32 FFMA, unchanged) ---------------- */
#define TS 68

__global__ void __launch_bounds__(256)
attn_kernel(float* __restrict__ wout, int write_w)
{
    extern __shared__ float sm[];
    float* Qt = sm;
    float* Kt = Qt + 64*TS;
    float* Wt = Kt + 64*TS;
    float* Vs = Wt + 64*TS;

    const int tid = threadIdx.x;
    const int tx = tid & 15, ty = tid >> 4;
    const int qt = blockIdx.x, h = blockIdx.y, b = blockIdx.z;
    const int q0 = qt * 64;
    const long basebh = (long)(b*NH + h) * SEQ;
    const float scale = 0.125f;

    {
        const float* Qg = g_Q + (basebh + q0) * HD;
        for (int f = tid; f < 1024; f += 256) {
            int r = f >> 4, dc = (f & 15) << 2;
            float4 v = *(const float4*)(Qg + r*HD + dc);
            Qt[(dc+0)*TS + r] = v.x;
            Qt[(dc+1)*TS + r] = v.y;
            Qt[(dc+2)*TS + r] = v.z;
            Qt[(dc+3)*TS + r] = v.w;
        }
    }
    __syncthreads();

    float mreg[4], lreg[4];
#pragma unroll
    for (int i = 0; i < 4; i++) { mreg[i] = -1e30f; lreg[i] = 0.f; }

    for (int kb = 0; kb <= qt; kb++) {
        const float* Kg = g_K + (basebh + kb*64) * HD;
        for (int f = tid; f < 1024; f += 256) {
            int r = f >> 4, dc = (f & 15) << 2;
            float4 v = *(const float4*)(Kg + r*HD + dc);
            Kt[(dc+0)*TS + r] = v.x;
            Kt[(dc+1)*TS + r] = v.y;
            Kt[(dc+2)*TS + r] = v.z;
            Kt[(dc+3)*TS + r] = v.w;
        }
        __syncthreads();

        float s[4][4];
#pragma unroll
        for (int i = 0; i < 4; i++)
#pragma unroll
            for (int j = 0; j < 4; j++) s[i][j] = 0.f;
#pragma unroll 16
        for (int d = 0; d < 64; d++) {
            float4 qa = *(const float4*)(Qt + d*TS + ty*4);
            float4 kv = *(const float4*)(Kt + d*TS + tx*4);
            float a[4] = {qa.x,qa.y,qa.z,qa.w};
            float c[4] = {kv.x,kv.y,kv.z,kv.w};
#pragma unroll
            for (int i = 0; i < 4; i++)
#pragma unroll
                for (int j = 0; j < 4; j++) s[i][j] = fmaf(a[i], c[j], s[i][j]);
        }
        int k0 = kb * 64;
#pragma unroll
        for (int i = 0; i < 4; i++) {
            int q = q0 + ty*4 + i;
#pragma unroll
            for (int j = 0; j < 4; j++) {
                int k = k0 + tx*4 + j;
                s[i][j] = (k <= q) ? s[i][j] * scale : -1e30f;
            }
            float tm = fmaxf(fmaxf(s[i][0], s[i][1]), fmaxf(s[i][2], s[i][3]));
#pragma unroll
            for (int off = 1; off < 16; off <<= 1)
                tm = fmaxf(tm, __shfl_xor_sync(0xffffffffu, tm, off));
            float mn = fmaxf(mreg[i], tm);
            float ps = expf(s[i][0]-mn) + expf(s[i][1]-mn)
                     + expf(s[i][2]-mn) + expf(s[i][3]-mn);
#pragma unroll
            for (int off = 1; off < 16; off <<= 1)
                ps += __shfl_xor_sync(0xffffffffu, ps, off);
            lreg[i] = lreg[i] * expf(mreg[i] - mn) + ps;
            mreg[i] = mn;
        }
        __syncthreads();
    }

    float inv_l[4];
#pragma unroll
    for (int i = 0; i < 4; i++) inv_l[i] = 1.f / lreg[i];

    float o[4][4];
#pragma unroll
    for (int i = 0; i < 4; i++)
#pragma unroll
        for (int j = 0; j < 4; j++) o[i][j] = 0.f;

    for (int kb = 0; kb <= qt; kb++) {
        const float* Kg = g_K + (basebh + kb*64) * HD;
        const float* Vg = g_V + (basebh + kb*64) * HD;
        for (int f = tid; f < 1024; f += 256) {
            int r = f >> 4, dc = (f & 15) << 2;
            float4 v = *(const float4*)(Kg + r*HD + dc);
            Kt[(dc+0)*TS + r] = v.x;
            Kt[(dc+1)*TS + r] = v.y;
            Kt[(dc+2)*TS + r] = v.z;
            Kt[(dc+3)*TS + r] = v.w;
            *(float4*)(Vs + r*64 + dc) = *(const float4*)(Vg + r*HD + dc);
        }
        __syncthreads();

        float s[4][4];
#pragma unroll
        for (int i = 0; i < 4; i++)
#pragma unroll
            for (int j = 0; j < 4; j++) s[i][j] = 0.f;
#pragma unroll 16
        for (int d = 0; d < 64; d++) {
            float4 qa = *(const float4*)(Qt + d*TS + ty*4);
            float4 kv = *(const float4*)(Kt + d*TS + tx*4);
            float a[4] = {qa.x,qa.y,qa.z,qa.w};
            float c[4] = {kv.x,kv.y,kv.z,kv.w};
#pragma unroll
            for (int i = 0; i < 4; i++)
#pragma unroll
                for (int j = 0; j < 4; j++) s[i][j] = fmaf(a[i], c[j], s[i][j]);
        }
        int k0 = kb * 64;
        float w[4][4];
#pragma unroll
        for (int i = 0; i < 4; i++) {
            int q = q0 + ty*4 + i;
#pragma unroll
            for (int j = 0; j < 4; j++) {
                int k = k0 + tx*4 + j;
                w[i][j] = (k <= q) ? expf(s[i][j]*scale - mreg[i]) * inv_l[i] : 0.f;
            }
        }
        if (write_w) {
#pragma unroll
            for (int i = 0; i < 4; i++) {
                long addr = (basebh + q0 + ty*4 + i) * (long)SEQ + k0 + tx*4;
                *(float4*)(wout + addr) = make_float4(w[i][0], w[i][1], w[i][2], w[i][3]);
            }
        }
#pragma unroll
        for (int i = 0; i < 4; i++)
#pragma unroll
            for (int j = 0; j < 4; j++)
                Wt[(tx*4+j)*TS + ty*4 + i] = w[i][j];
        __syncthreads();

#pragma unroll 16
        for (int c = 0; c < 64; c++) {
            float4 wa = *(const float4*)(Wt + c*TS + ty*4);
            float4 vv = *(const float4*)(Vs + c*64 + tx*4);
            float a[4] = {wa.x,wa.y,wa.z,wa.w};
            float v2[4] = {vv.x,vv.y,vv.z,vv.w};
#pragma unroll
            for (int i = 0; i < 4; i++)
#pragma unroll
                for (int j = 0; j < 4; j++) o[i][j] = fmaf(a[i], v2[j], o[i][j]);
        }
        __syncthreads();
    }

    if (write_w) {
        float4 z4 = make_float4(0.f, 0.f, 0.f, 0.f);
        for (int kb = qt + 1; kb < SEQ/64; kb++) {
            for (int f = tid; f < 1024; f += 256) {
                int r = f >> 4, cc = (f & 15) << 2;
                *(float4*)(wout + (basebh + q0 + r) * (long)SEQ + kb*64 + cc) = z4;
            }
        }
    }

#pragma unroll
    for (int i = 0; i < 4; i++) {
        long addr = ((long)(b*SEQ + q0 + ty*4 + i)) * HID + h*HD + tx*4;
        *(float4*)(g_attn + addr) = make_float4(o[i][0], o[i][1], o[i][2], o[i][3]);
    }
}

/* ---------------- launcher ---------------- */
extern "C" void kernel_launch(void* const* d_in, const int* in_sizes, int n_in,
                              void* d_out, int out_size)
{
    const float* q  = (const float*)d_in[0];
    const float* k  = (const float*)d_in[1];
    const float* v  = (const float*)d_in[2];
    const float* Wq = (const float*)d_in[3];
    const float* bq = (const float*)d_in[4];
    const float* Wk = (const float*)d_in[5];
    const float* bk = (const float*)d_in[6];
    const float* Wv = (const float*)d_in[7];
    const float* bv = (const float*)d_in[8];
    const float* Wo = (const float*)d_in[9];
    const float* bo = (const float*)d_in[10];

    float* out  = (float*)d_out;
    int write_w = (out_size >= OUT_ELEMS + W_ELEMS) ? 1 : 0;
    float* wout = out + OUT_ELEMS;

    __nv_bfloat16 *p_sq, *p_sk, *p_sv, *p_swq, *p_swk, *p_swv, *p_swo, *p_sat;
    float *p_gattn, *p_gQ, *p_gK, *p_gV;
    cudaGetSymbolAddress((void**)&p_sq,  s_q);
    cudaGetSymbolAddress((void**)&p_sk,  s_k);
    cudaGetSymbolAddress((void**)&p_sv,  s_v);
    cudaGetSymbolAddress((void**)&p_swq, s_wq);
    cudaGetSymbolAddress((void**)&p_swk, s_wk);
    cudaGetSymbolAddress((void**)&p_swv, s_wv);
    cudaGetSymbolAddress((void**)&p_swo, s_wo);
    cudaGetSymbolAddress((void**)&p_sat, s_at);
    cudaGetSymbolAddress((void**)&p_gattn, g_attn);
    cudaGetSymbolAddress((void**)&p_gQ, g_Q);
    cudaGetSymbolAddress((void**)&p_gK, g_K);
    cudaGetSymbolAddress((void**)&p_gV, g_V);

    rope_table_kernel<<<(SEQ*32 + 255)/256, 256>>>();

    const int nIn = MTOT * HID;
    const int nW  = HID * HID;
    split_a_kernel<<<(nIn+255)/256, 256>>>(q,  p_sq,  nIn);
    split_a_kernel<<<(nIn+255)/256, 256>>>(k,  p_sk,  nIn);
    split_a_kernel<<<(nIn+255)/256, 256>>>(v,  p_sv,  nIn);
    split_b_kernel<<<(nW +255)/256, 256>>>(Wq, p_swq, nW);
    split_b_kernel<<<(nW +255)/256, 256>>>(Wk, p_swk, nW);
    split_b_kernel<<<(nW +255)/256, 256>>>(Wv, p_swv, nW);
    split_b_kernel<<<(nW +255)/256, 256>>>(Wo, p_swo, nW);

    dim3 ggrid(HID/128, MTOT/128);   /* (8, 32) */
    gemm_mma<<<ggrid, 256>>>(p_sq, p_swq, bq, p_gQ, 0);
    gemm_mma<<<ggrid, 256>>>(p_sk, p_swk, bk, p_gK, 0);
    gemm_mma<<<ggrid, 256>>>(p_sv, p_swv, bv, p_gV, 1);

    size_t smem = (size_t)(3*64*TS + 64*64) * sizeof(float);
    cudaFuncSetAttribute(attn_kernel,
                         cudaFuncAttributeMaxDynamicSharedMemorySize, (int)smem);
    attn_kernel<<<dim3(SEQ/64, NH, BATCH), 256, smem>>>(wout, write_w);

    split_a_kernel<<<(nIn+255)/256, 256>>>(p_gattn, p_sat, nIn);
    gemm_mma<<<ggrid, 256>>>(p_sat, p_swo, bo, out, 2);
}

// round 4
// speedup vs baseline: 2.2543x; 1.8226x over previous
#include <cuda_runtime.h>
#include <cuda_bf16.h>
#include <math.h>
#include <stdint.h>

#define BATCH 2
#define SEQ   2048
#define HID   1024
#define NH    16
#define HD    64
#define MTOT  (BATCH*SEQ)
#define OUT_ELEMS   (MTOT*HID)
#define W_ELEMS     (BATCH*NH*SEQ*SEQ)
#define KS3   3072               /* split-K: [hi | lo | hi] x 1024 */
#define LOG2E 1.44269504088896340736f

/* ---------------- scratch (no allocations allowed) ---------------- */
__device__ float g_cos[SEQ*(HD/2)];
__device__ float g_sin[SEQ*(HD/2)];

/* Q/K/V in (B,H,S,D) as bf16 hi/lo pairs */
__device__ __nv_bfloat16 g_Qh[BATCH*NH*SEQ*HD];
__device__ __nv_bfloat16 g_Ql[BATCH*NH*SEQ*HD];
__device__ __nv_bfloat16 g_Kh[BATCH*NH*SEQ*HD];
__device__ __nv_bfloat16 g_Kl[BATCH*NH*SEQ*HD];
__device__ __nv_bfloat16 g_Vh[BATCH*NH*SEQ*HD];
__device__ __nv_bfloat16 g_Vl[BATCH*NH*SEQ*HD];

/* bf16 split operands for projections (A: [ah|al|ah], B: [bh|bh|bl]) */
__device__ __nv_bfloat16 s_q [MTOT*KS3];
__device__ __nv_bfloat16 s_k [MTOT*KS3];
__device__ __nv_bfloat16 s_v [MTOT*KS3];
__device__ __nv_bfloat16 s_at[MTOT*KS3];
__device__ __nv_bfloat16 s_wq[HID*KS3];
__device__ __nv_bfloat16 s_wk[HID*KS3];
__device__ __nv_bfloat16 s_wv[HID*KS3];
__device__ __nv_bfloat16 s_wo[HID*KS3];

/* ---------------- mma.sync / ldmatrix helpers ---------------- */
__device__ __forceinline__ uint32_t smem_u32(const void* p) {
    uint32_t a;
    asm("{ .reg .u64 t; cvta.to.shared.u64 t, %1; cvt.u32.u64 %0, t; }"
        : "=r"(a) : "l"(p));
    return a;
}
__device__ __forceinline__ void ldsm4(uint32_t& r0, uint32_t& r1,
                                      uint32_t& r2, uint32_t& r3, uint32_t addr)
{
    asm volatile("ldmatrix.sync.aligned.m8n8.x4.shared.b16 {%0,%1,%2,%3}, [%4];"
                 : "=r"(r0), "=r"(r1), "=r"(r2), "=r"(r3) : "r"(addr));
}
__device__ __forceinline__ void ldsm4t(uint32_t& r0, uint32_t& r1,
                                       uint32_t& r2, uint32_t& r3, uint32_t addr)
{
    asm volatile("ldmatrix.sync.aligned.m8n8.x4.trans.shared.b16 {%0,%1,%2,%3}, [%4];"
                 : "=r"(r0), "=r"(r1), "=r"(r2), "=r"(r3) : "r"(addr));
}
__device__ __forceinline__ void mma_bf16(float* d, const uint32_t* a,
                                         uint32_t b0, uint32_t b1)
{
    asm volatile(
        "mma.sync.aligned.m16n8k16.row.col.f32.bf16.bf16.f32 "
        "{%0,%1,%2,%3}, {%4,%5,%6,%7}, {%8,%9}, {%0,%1,%2,%3};"
        : "+f"(d[0]), "+f"(d[1]), "+f"(d[2]), "+f"(d[3])
        : "r"(a[0]), "r"(a[1]), "r"(a[2]), "r"(a[3]), "r"(b0), "r"(b1));
}
__device__ __forceinline__ float ex2(float x) {
    float y;
    asm("ex2.approx.ftz.f32 %0, %1;" : "=f"(y) : "f"(x));
    return y;
}
__device__ __forceinline__ uint32_t pack_bf2(float x, float y) {
    __nv_bfloat162 t = __floats2bfloat162_rn(x, y);
    return *(uint32_t*)&t;
}

/* ---------------- RoPE tables (double precision) ----------------- */
__global__ void rope_table_kernel() {
    int idx = blockIdx.x * blockDim.x + threadIdx.x;
    if (idx >= SEQ * (HD/2)) return;
    int s = idx >> 5;
    int j = idx & 31;
    double inv = exp(-((double)(2*j) / (double)HD) * log(10000.0));
    double ang = (double)s * inv;
    g_cos[idx] = (float)cos(ang);
    g_sin[idx] = (float)sin(ang);
}

/* -------- fp32 -> bf16 split, A-format: [hi | lo | hi] ----------- */
__global__ void __launch_bounds__(256)
split_a_kernel(const float* __restrict__ src, __nv_bfloat16* __restrict__ dst, int n)
{
    int idx = blockIdx.x * blockDim.x + threadIdx.x;
    if (idx >= n) return;
    float x = src[idx];
    int row = idx >> 10, kk = idx & 1023;
    int blk = kk >> 5,  j  = kk & 31;
    __nv_bfloat16 hi = __float2bfloat16(x);
    __nv_bfloat16 lo = __float2bfloat16(x - __bfloat162float(hi));
    size_t base = (size_t)row * KS3 + blk*96 + j;
    dst[base]      = hi;
    dst[base + 32] = lo;
    dst[base + 64] = hi;
}
/* -------- fp32 -> bf16 split, B-format: [hi | hi | lo] ----------- */
__global__ void __launch_bounds__(256)
split_b_kernel(const float* __restrict__ src, __nv_bfloat16* __restrict__ dst, int n)
{
    int idx = blockIdx.x * blockDim.x + threadIdx.x;
    if (idx >= n) return;
    float x = src[idx];
    int row = idx >> 10, kk = idx & 1023;
    int blk = kk >> 5,  j  = kk & 31;
    __nv_bfloat16 hi = __float2bfloat16(x);
    __nv_bfloat16 lo = __float2bfloat16(x - __bfloat162float(hi));
    size_t base = (size_t)row * KS3 + blk*96 + j;
    dst[base]      = hi;
    dst[base + 32] = hi;
    dst[base + 64] = lo;
}

/* ================= mma.sync bf16 GEMM =================
   C[m,n] = sum_{k<3072} A[m,k] * B[n,k]  (fp32-via-split).
   CTA tile 128x128, 256 threads = 8 warps (4x2), warp tile 32x64.
   mode 0: +bias, RoPE, split-write hi/lo (B,H,S,D)
   mode 1: +bias,       split-write hi/lo (B,H,S,D)
   mode 2: +bias,       fp32 write row-major [M x 1024]               */
#define SSTR 72                       /* smem row stride in bf16 */

__global__ void __launch_bounds__(256)
gemm_mma(const __nv_bfloat16* __restrict__ A,
         const __nv_bfloat16* __restrict__ B,
         const float* __restrict__ bias,
         float* __restrict__ dst,
         __nv_bfloat16* __restrict__ dhi,
         __nv_bfloat16* __restrict__ dlo, int mode)
{
    __shared__ __align__(16) __nv_bfloat16 As[128*SSTR];
    __shared__ __align__(16) __nv_bfloat16 Bs[128*SSTR];

    const int tid = threadIdx.x;
    const int wid = tid >> 5, l = tid & 31;
    const int warp_m = wid >> 1, warp_n = wid & 1;
    const int m0 = blockIdx.y * 128;
    const int n0 = blockIdx.x * 128;

    const uint32_t asb = smem_u32(As);
    const uint32_t bsb = smem_u32(Bs);

    const uint4* gA = (const uint4*)(A + (size_t)m0 * KS3);
    const uint4* gB = (const uint4*)(B + (size_t)n0 * KS3);

    float acc[2][8][4];
#pragma unroll
    for (int i = 0; i < 2; i++)
#pragma unroll
        for (int j = 0; j < 8; j++)
#pragma unroll
            for (int p = 0; p < 4; p++) acc[i][j][p] = 0.f;

    uint32_t a_addr[2], b_addr[4];
#pragma unroll
    for (int mt = 0; mt < 2; mt++) {
        int row = warp_m*32 + mt*16 + (l & 15);
        int col = (l >> 4) * 8;
        a_addr[mt] = asb + (row*SSTR + col) * 2;
    }
#pragma unroll
    for (int nt = 0; nt < 4; nt++) {
        int row = warp_n*64 + nt*16 + (l & 7) + ((l >> 4) & 1) * 8;
        int col = ((l >> 3) & 1) * 8;
        b_addr[nt] = bsb + (row*SSTR + col) * 2;
    }

    for (int it = 0; it < KS3/64; it++) {
        if (it) __syncthreads();
#pragma unroll
        for (int u = 0; u < 4; u++) {
            int f = u * 256 + tid;
            int r = f >> 3, c = f & 7;
            ((uint4*)As)[r*(SSTR/8) + c] = gA[(size_t)r*(KS3/8) + it*8 + c];
            ((uint4*)Bs)[r*(SSTR/8) + c] = gB[(size_t)r*(KS3/8) + it*8 + c];
        }
        __syncthreads();

#pragma unroll
        for (int ks = 0; ks < 4; ks++) {
            uint32_t a[2][4], b[4][4];
#pragma unroll
            for (int mt = 0; mt < 2; mt++)
                ldsm4(a[mt][0], a[mt][1], a[mt][2], a[mt][3],
                      a_addr[mt] + ks*32);
#pragma unroll
            for (int nt = 0; nt < 4; nt++)
                ldsm4(b[nt][0], b[nt][1], b[nt][2], b[nt][3],
                      b_addr[nt] + ks*32);
#pragma unroll
            for (int mt = 0; mt < 2; mt++)
#pragma unroll
                for (int nt = 0; nt < 4; nt++) {
                    mma_bf16(acc[mt][nt*2],   a[mt], b[nt][0], b[nt][1]);
                    mma_bf16(acc[mt][nt*2+1], a[mt], b[nt][2], b[nt][3]);
                }
        }
    }

    /* ---------------- epilogue ---------------- */
    const int g = l >> 2, q = l & 3;
#pragma unroll
    for (int mt = 0; mt < 2; mt++) {
        int mrow0 = m0 + warp_m*32 + mt*16 + g;
#pragma unroll
        for (int nt2 = 0; nt2 < 8; nt2++) {
            int ncol = n0 + warp_n*64 + nt2*8 + q*2;
            float b0 = bias[ncol], b1 = bias[ncol+1];
            float c0 = acc[mt][nt2][0] + b0;
            float c1 = acc[mt][nt2][1] + b1;
            float c2 = acc[mt][nt2][2] + b0;
            float c3 = acc[mt][nt2][3] + b1;

            if (mode == 2) {
                *(float2*)(dst + (size_t)mrow0    *HID + ncol) = make_float2(c0, c1);
                *(float2*)(dst + (size_t)(mrow0+8)*HID + ncol) = make_float2(c2, c3);
            } else {
                int h = ncol >> 6, d = ncol & 63;
                int bb0 = mrow0 >> 11, ss0 = mrow0 & 2047;
                int mrow1 = mrow0 + 8;
                int bb1 = mrow1 >> 11, ss1 = mrow1 & 2047;
                if (mode == 0) {
                    float cs0 = g_cos[ss0*32 + (d>>1)], sn0 = g_sin[ss0*32 + (d>>1)];
                    float cs1 = g_cos[ss1*32 + (d>>1)], sn1 = g_sin[ss1*32 + (d>>1)];
                    float t0 = c0*cs0 - c1*sn0, t1 = c0*sn0 + c1*cs0;
                    float t2 = c2*cs1 - c3*sn1, t3 = c2*sn1 + c3*cs1;
                    c0 = t0; c1 = t1; c2 = t2; c3 = t3;
                }
                size_t a0 = (((size_t)(bb0*NH + h)*SEQ + ss0) << 6) + d;
                size_t a1 = (((size_t)(bb1*NH + h)*SEQ + ss1) << 6) + d;
                __nv_bfloat16 h0 = __float2bfloat16(c0);
                __nv_bfloat16 h1 = __float2bfloat16(c1);
                __nv_bfloat16 h2 = __float2bfloat16(c2);
                __nv_bfloat16 h3 = __float2bfloat16(c3);
                *(__nv_bfloat162*)(dhi + a0) = __halves2bfloat162(h0, h1);
                *(__nv_bfloat162*)(dhi + a1) = __halves2bfloat162(h2, h3);
                *(__nv_bfloat162*)(dlo + a0) = __floats2bfloat162_rn(
                    c0 - __bfloat162float(h0), c1 - __bfloat162float(h1));
                *(__nv_bfloat162*)(dlo + a1) = __floats2bfloat162_rn(
                    c2 - __bfloat162float(h2), c3 - __bfloat162float(h3));
            }
        }
    }
}

/* ================= attention via mma.sync =================
   One block per (q-tile of 128, head, batch). 256 threads = 8 warps,
   warp w owns q-rows [q0+16w, q0+16w+16). K/V tiles of 64.
   Pass 1: scores (3-term bf16 split) -> online row max/sum.
   Pass 2: recompute scores, w = exp2(s*c - m)/l -> gmem weights,
           O += W@V (3-term split, W frags straight from accumulators,
           V frags via ldmatrix.trans). O written in split-A format.  */
/* dyn smem layout (bytes): Qh 0..18432, Ql ..36864, Kh ..46080,
   Kl ..55296, Vh ..64512, Vl ..73728                                  */
#define AQH 0
#define AQL 18432
#define AKH 36864
#define AKL 46080
#define AVH 55296
#define AVL 64512
#define ASMEM 73728

__global__ void __launch_bounds__(256)
attn_mma(float* __restrict__ wout, int write_w)
{
    extern __shared__ __align__(16) char dsm[];
    const int tid = threadIdx.x;
    const int w = tid >> 5, l = tid & 31;
    const int g = l >> 2, q = l & 3;
    const int qt = blockIdx.x, h = blockIdx.y, b = blockIdx.z;
    const int q0 = qt * 128;
    const size_t basebh = (size_t)(b*NH + h) * SEQ;
    const uint32_t sb = smem_u32(dsm);

    /* load Q tiles (hi & lo), 128 rows x 64 bf16, smem stride 144B */
    {
        const uint4* gh = (const uint4*)(g_Qh + (basebh + q0) * HD);
        const uint4* gl = (const uint4*)(g_Ql + (basebh + q0) * HD);
        uint4* sh = (uint4*)(dsm + AQH);
        uint4* sl = (uint4*)(dsm + AQL);
#pragma unroll
        for (int u = 0; u < 4; u++) {
            int f = u*256 + tid;
            int r = f >> 3, c = f & 7;
            sh[r*9 + c] = gh[r*8 + c];
            sl[r*9 + c] = gl[r*8 + c];
        }
    }

    const uint32_t aQh = sb + AQH + (w*16 + (l & 15))*144 + (l >> 4)*16;
    const uint32_t aQl = aQh + (AQL - AQH);
    uint32_t bK[4];
    {
        int krow = (l & 7) + ((l >> 4) & 1) * 8;
        int kcb  = ((l >> 3) & 1) * 16;
#pragma unroll
        for (int nt = 0; nt < 4; nt++)
            bK[nt] = sb + AKH + (nt*16 + krow)*144 + kcb;
    }
    const uint32_t aV = sb + AVH + (l & 15)*144 + (l >> 4)*16;

    const float CE = 0.125f * LOG2E;
    const int nkt = 2*qt + 2;
    const int rw0 = q0 + w*16;
    const int r0 = rw0 + g, r1 = r0 + 8;

    float m2[2] = {-1e30f, -1e30f};
    float l2[2] = {0.f, 0.f};

    /* ---------------- PASS 1: row max & sum ---------------- */
    for (int kb = 0; kb < nkt; kb++) {
        __syncthreads();
        {
            const uint4* gkh = (const uint4*)(g_Kh + (basebh + kb*64) * HD);
            const uint4* gkl = (const uint4*)(g_Kl + (basebh + kb*64) * HD);
            uint4* skh = (uint4*)(dsm + AKH);
            uint4* skl = (uint4*)(dsm + AKL);
#pragma unroll
            for (int u = 0; u < 2; u++) {
                int f = u*256 + tid;
                int r = f >> 3, c = f & 7;
                skh[r*9 + c] = gkh[r*8 + c];
                skl[r*9 + c] = gkl[r*8 + c];
            }
        }
        __syncthreads();

        float acc[8][4];
#pragma unroll
        for (int nt = 0; nt < 8; nt++)
#pragma unroll
            for (int p = 0; p < 4; p++) acc[nt][p] = 0.f;

#pragma unroll
        for (int ks = 0; ks < 4; ks++) {
            uint32_t ah[4], al[4];
            ldsm4(ah[0], ah[1], ah[2], ah[3], aQh + ks*32);
            ldsm4(al[0], al[1], al[2], al[3], aQl + ks*32);
#pragma unroll
            for (int np = 0; np < 4; np++) {
                uint32_t kh[4], kl[4];
                ldsm4(kh[0], kh[1], kh[2], kh[3], bK[np] + ks*32);
                ldsm4(kl[0], kl[1], kl[2], kl[3], bK[np] + (AKL-AKH) + ks*32);
                mma_bf16(acc[np*2],   ah, kh[0], kh[1]);
                mma_bf16(acc[np*2+1], ah, kh[2], kh[3]);
                mma_bf16(acc[np*2],   al, kh[0], kh[1]);
                mma_bf16(acc[np*2+1], al, kh[2], kh[3]);
                mma_bf16(acc[np*2],   ah, kl[0], kl[1]);
                mma_bf16(acc[np*2+1], ah, kl[2], kl[3]);
            }
        }

        const bool needmask = (kb*64 + 63) > rw0;
#pragma unroll
        for (int nt = 0; nt < 8; nt++) {
            int k0c = kb*64 + nt*8 + q*2;
            acc[nt][0] = (!needmask || k0c   <= r0) ? acc[nt][0]*CE : -1e30f;
            acc[nt][1] = (!needmask || k0c+1 <= r0) ? acc[nt][1]*CE : -1e30f;
            acc[nt][2] = (!needmask || k0c   <= r1) ? acc[nt][2]*CE : -1e30f;
            acc[nt][3] = (!needmask || k0c+1 <= r1) ? acc[nt][3]*CE : -1e30f;
        }
        float tm0 = -1e30f, tm1 = -1e30f;
#pragma unroll
        for (int nt = 0; nt < 8; nt++) {
            tm0 = fmaxf(tm0, fmaxf(acc[nt][0], acc[nt][1]));
            tm1 = fmaxf(tm1, fmaxf(acc[nt][2], acc[nt][3]));
        }
        tm0 = fmaxf(tm0, __shfl_xor_sync(0xffffffffu, tm0, 1));
        tm0 = fmaxf(tm0, __shfl_xor_sync(0xffffffffu, tm0, 2));
        tm1 = fmaxf(tm1, __shfl_xor_sync(0xffffffffu, tm1, 1));
        tm1 = fmaxf(tm1, __shfl_xor_sync(0xffffffffu, tm1, 2));
        float mn0 = fmaxf(m2[0], tm0), mn1 = fmaxf(m2[1], tm1);
        float s0 = 0.f, s1 = 0.f;
#pragma unroll
        for (int nt = 0; nt < 8; nt++) {
            s0 += ex2(acc[nt][0] - mn0) + ex2(acc[nt][1] - mn0);
            s1 += ex2(acc[nt][2] - mn1) + ex2(acc[nt][3] - mn1);
        }
        s0 += __shfl_xor_sync(0xffffffffu, s0, 1);
        s0 += __shfl_xor_sync(0xffffffffu, s0, 2);
        s1 += __shfl_xor_sync(0xffffffffu, s1, 1);
        s1 += __shfl_xor_sync(0xffffffffu, s1, 2);
        l2[0] = l2[0] * ex2(m2[0] - mn0) + s0;  m2[0] = mn0;
        l2[1] = l2[1] * ex2(m2[1] - mn1) + s1;  m2[1] = mn1;
    }

    const float invl0 = 1.f / l2[0];
    const float invl1 = 1.f / l2[1];

    float o[8][4];
#pragma unroll
    for (int nd = 0; nd < 8; nd++)
#pragma unroll
        for (int p = 0; p < 4; p++) o[nd][p] = 0.f;

    /* ---------------- PASS 2: weights + O ---------------- */
    for (int kb = 0; kb < nkt; kb++) {
        __syncthreads();
        {
            const uint4* gkh = (const uint4*)(g_Kh + (basebh + kb*64) * HD);
            const uint4* gkl = (const uint4*)(g_Kl + (basebh + kb*64) * HD);
            const uint4* gvh = (const uint4*)(g_Vh + (basebh + kb*64) * HD);
            const uint4* gvl = (const uint4*)(g_Vl + (basebh + kb*64) * HD);
            uint4* skh = (uint4*)(dsm + AKH);
            uint4* skl = (uint4*)(dsm + AKL);
            uint4* svh = (uint4*)(dsm + AVH);
            uint4* svl = (uint4*)(dsm + AVL);
#pragma unroll
            for (int u = 0; u < 2; u++) {
                int f = u*256 + tid;
                int r = f >> 3, c = f & 7;
                skh[r*9 + c] = gkh[r*8 + c];
                skl[r*9 + c] = gkl[r*8 + c];
                svh[r*9 + c] = gvh[r*8 + c];
                svl[r*9 + c] = gvl[r*8 + c];
            }
        }
        __syncthreads();

        float acc[8][4];
#pragma unroll
        for (int nt = 0; nt < 8; nt++)
#pragma unroll
            for (int p = 0; p < 4; p++) acc[nt][p] = 0.f;

#pragma unroll
        for (int ks = 0; ks < 4; ks++) {
            uint32_t ah[4], al[4];
            ldsm4(ah[0], ah[1], ah[2], ah[3], aQh + ks*32);
            ldsm4(al[0], al[1], al[2], al[3], aQl + ks*32);
#pragma unroll
            for (int np = 0; np < 4; np++) {
                uint32_t kh[4], kl[4];
                ldsm4(kh[0], kh[1], kh[2], kh[3], bK[np] + ks*32);
                ldsm4(kl[0], kl[1], kl[2], kl[3], bK[np] + (AKL-AKH) + ks*32);
                mma_bf16(acc[np*2],   ah, kh[0], kh[1]);
                mma_bf16(acc[np*2+1], ah, kh[2], kh[3]);
                mma_bf16(acc[np*2],   al, kh[0], kh[1]);
                mma_bf16(acc[np*2+1], al, kh[2], kh[3]);
                mma_bf16(acc[np*2],   ah, kl[0], kl[1]);
                mma_bf16(acc[np*2+1], ah, kl[2], kl[3]);
            }
        }

        const bool needmask = (kb*64 + 63) > rw0;
#pragma unroll
        for (int nt = 0; nt < 8; nt++) {
            int k0c = kb*64 + nt*8 + q*2;
            float w0 = (!needmask || k0c   <= r0)
                       ? ex2(acc[nt][0]*CE - m2[0]) * invl0 : 0.f;
            float w1 = (!needmask || k0c+1 <= r0)
                       ? ex2(acc[nt][1]*CE - m2[0]) * invl0 : 0.f;
            float w2 = (!needmask || k0c   <= r1)
                       ? ex2(acc[nt][2]*CE - m2[1]) * invl1 : 0.f;
            float w3 = (!needmask || k0c+1 <= r1)
                       ? ex2(acc[nt][3]*CE - m2[1]) * invl1 : 0.f;
            acc[nt][0] = w0; acc[nt][1] = w1; acc[nt][2] = w2; acc[nt][3] = w3;
            if (write_w) {
                *(float2*)(wout + (basebh + r0)*SEQ + k0c) = make_float2(w0, w1);
                *(float2*)(wout + (basebh + r1)*SEQ + k0c) = make_float2(w2, w3);
            }
        }

        /* PV: W fragments straight from acc */
#pragma unroll
        for (int t = 0; t < 4; t++) {
            uint32_t awh[4], awl[4];
            {
                float c0 = acc[2*t][0],   c1 = acc[2*t][1];
                float c2 = acc[2*t][2],   c3 = acc[2*t][3];
                float d0 = acc[2*t+1][0], d1 = acc[2*t+1][1];
                float d2 = acc[2*t+1][2], d3 = acc[2*t+1][3];
                awh[0] = pack_bf2(c0, c1);
                awh[1] = pack_bf2(c2, c3);
                awh[2] = pack_bf2(d0, d1);
                awh[3] = pack_bf2(d2, d3);
                __nv_bfloat162* ph;
                ph = (__nv_bfloat162*)&awh[0];
                awl[0] = pack_bf2(c0 - __bfloat162float(ph->x),
                                  c1 - __bfloat162float(ph->y));
                ph = (__nv_bfloat162*)&awh[1];
                awl[1] = pack_bf2(c2 - __bfloat162float(ph->x),
                                  c3 - __bfloat162float(ph->y));
                ph = (__nv_bfloat162*)&awh[2];
                awl[2] = pack_bf2(d0 - __bfloat162float(ph->x),
                                  d1 - __bfloat162float(ph->y));
                ph = (__nv_bfloat162*)&awh[3];
                awl[3] = pack_bf2(d2 - __bfloat162float(ph->x),
                                  d3 - __bfloat162float(ph->y));
            }
#pragma unroll
            for (int nd = 0; nd < 4; nd++) {
                uint32_t vh[4], vl[4];
                ldsm4t(vh[0], vh[1], vh[2], vh[3], aV + t*2304 + nd*32);
                ldsm4t(vl[0], vl[1], vl[2], vl[3],
                       aV + (AVL-AVH) + t*2304 + nd*32);
                mma_bf16(o[nd*2],   awh, vh[0], vh[1]);
                mma_bf16(o[nd*2+1], awh, vh[2], vh[3]);
                mma_bf16(o[nd*2],   awl, vh[0], vh[1]);
                mma_bf16(o[nd*2+1], awl, vh[2], vh[3]);
                mma_bf16(o[nd*2],   awh, vl[0], vl[1]);
                mma_bf16(o[nd*2+1], awh, vl[2], vl[3]);
            }
        }
    }

    /* zero-fill the masked (upper-triangle) region */
    if (write_w) {
        int kend = q0 + 128;
        int rem = SEQ - kend;
        if (rem > 0) {
            int nf4 = rem >> 2;
            float4 z4 = make_float4(0.f, 0.f, 0.f, 0.f);
            for (int f = tid; f < 128*nf4; f += 256) {
                int r = f / nf4, cc = (f - r*nf4) * 4;
                *(float4*)(wout + (basebh + q0 + r)*SEQ + kend + cc) = z4;
            }
        }
    }

    /* write O in split-A format for the output projection */
    {
        size_t mg0 = (size_t)b*SEQ + q0 + w*16 + g;
        size_t mg1 = mg0 + 8;
#pragma unroll
        for (int nd = 0; nd < 8; nd++) {
            int col = h*64 + nd*8 + q*2;
            int blk = col >> 5, j = col & 31;
            size_t b0 = mg0*KS3 + blk*96 + j;
            size_t b1 = mg1*KS3 + blk*96 + j;
            float c0 = o[nd][0], c1 = o[nd][1];
            float c2 = o[nd][2], c3 = o[nd][3];
            __nv_bfloat16 h0 = __float2bfloat16(c0);
            __nv_bfloat16 h1 = __float2bfloat16(c1);
            __nv_bfloat16 h2 = __float2bfloat16(c2);
            __nv_bfloat16 h3 = __float2bfloat16(c3);
            __nv_bfloat162 hi0 = __halves2bfloat162(h0, h1);
            __nv_bfloat162 hi1 = __halves2bfloat162(h2, h3);
            __nv_bfloat162 lo0 = __floats2bfloat162_rn(
                c0 - __bfloat162float(h0), c1 - __bfloat162float(h1));
            __nv_bfloat162 lo1 = __floats2bfloat162_rn(
                c2 - __bfloat162float(h2), c3 - __bfloat162float(h3));
            *(__nv_bfloat162*)(s_at + b0)      = hi0;
            *(__nv_bfloat162*)(s_at + b0 + 32) = lo0;
            *(__nv_bfloat162*)(s_at + b0 + 64) = hi0;
            *(__nv_bfloat162*)(s_at + b1)      = hi1;
            *(__nv_bfloat162*)(s_at + b1 + 32) = lo1;
            *(__nv_bfloat162*)(s_at + b1 + 64) = hi1;
        }
    }
}

/* ---------------- launcher ---------------- */
extern "C" void kernel_launch(void* const* d_in, const int* in_sizes, int n_in,
                              void* d_out, int out_size)
{
    const float* q  = (const float*)d_in[0];
    const float* k  = (const float*)d_in[1];
    const float* v  = (const float*)d_in[2];
    const float* Wq = (const float*)d_in[3];
    const float* bq = (const float*)d_in[4];
    const float* Wk = (const float*)d_in[5];
    const float* bk = (const float*)d_in[6];
    const float* Wv = (const float*)d_in[7];
    const float* bv = (const float*)d_in[8];
    const float* Wo = (const float*)d_in[9];
    const float* bo = (const float*)d_in[10];

    float* out  = (float*)d_out;
    int write_w = (out_size >= OUT_ELEMS + W_ELEMS) ? 1 : 0;
    float* wout = out + OUT_ELEMS;

    __nv_bfloat16 *p_sq, *p_sk, *p_sv, *p_swq, *p_swk, *p_swv, *p_swo, *p_sat;
    __nv_bfloat16 *p_qh, *p_ql, *p_kh, *p_kl, *p_vh, *p_vl;
    cudaGetSymbolAddress((void**)&p_sq,  s_q);
    cudaGetSymbolAddress((void**)&p_sk,  s_k);
    cudaGetSymbolAddress((void**)&p_sv,  s_v);
    cudaGetSymbolAddress((void**)&p_swq, s_wq);
    cudaGetSymbolAddress((void**)&p_swk, s_wk);
    cudaGetSymbolAddress((void**)&p_swv, s_wv);
    cudaGetSymbolAddress((void**)&p_swo, s_wo);
    cudaGetSymbolAddress((void**)&p_sat, s_at);
    cudaGetSymbolAddress((void**)&p_qh, g_Qh);
    cudaGetSymbolAddress((void**)&p_ql, g_Ql);
    cudaGetSymbolAddress((void**)&p_kh, g_Kh);
    cudaGetSymbolAddress((void**)&p_kl, g_Kl);
    cudaGetSymbolAddress((void**)&p_vh, g_Vh);
    cudaGetSymbolAddress((void**)&p_vl, g_Vl);

    rope_table_kernel<<<(SEQ*32 + 255)/256, 256>>>();

    const int nIn = MTOT * HID;
    const int nW  = HID * HID;
    split_a_kernel<<<(nIn+255)/256, 256>>>(q,  p_sq,  nIn);
    split_a_kernel<<<(nIn+255)/256, 256>>>(k,  p_sk,  nIn);
    split_a_kernel<<<(nIn+255)/256, 256>>>(v,  p_sv,  nIn);
    split_b_kernel<<<(nW +255)/256, 256>>>(Wq, p_swq, nW);
    split_b_kernel<<<(nW +255)/256, 256>>>(Wk, p_swk, nW);
    split_b_kernel<<<(nW +255)/256, 256>>>(Wv, p_swv, nW);
    split_b_kernel<<<(nW +255)/256, 256>>>(Wo, p_swo, nW);

    dim3 ggrid(HID/128, MTOT/128);   /* (8, 32) */
    gemm_mma<<<ggrid, 256>>>(p_sq, p_swq, bq, nullptr, p_qh, p_ql, 0);
    gemm_mma<<<ggrid, 256>>>(p_sk, p_swk, bk, nullptr, p_kh, p_kl, 0);
    gemm_mma<<<ggrid, 256>>>(p_sv, p_swv, bv, nullptr, p_vh, p_vl, 1);

    cudaFuncSetAttribute(attn_mma,
                         cudaFuncAttributeMaxDynamicSharedMemorySize, ASMEM);
    attn_mma<<<dim3(SEQ/128, NH, BATCH), 256, ASMEM>>>(wout, write_w);

    gemm_mma<<<ggrid, 256>>>(p_sat, p_swo, bo, out, nullptr, nullptr, 2);
}

// round 5
// speedup vs baseline: 2.3286x; 1.0330x over previous
#include <cuda_runtime.h>
#include <cuda_bf16.h>
#include <math.h>
#include <stdint.h>

#define BATCH 2
#define SEQ   2048
#define HID   1024
#define NH    16
#define HD    64
#define MTOT  (BATCH*SEQ)
#define OUT_ELEMS   (MTOT*HID)
#define W_ELEMS     (BATCH*NH*SEQ*SEQ)
#define KS3   3072               /* split-K: [hi | lo | hi] x 1024 */
#define LOG2E 1.44269504088896340736f

/* ---------------- scratch (no allocations allowed) ---------------- */
__device__ float g_cos[SEQ*(HD/2)];
__device__ float g_sin[SEQ*(HD/2)];

__device__ __nv_bfloat16 g_Qh[BATCH*NH*SEQ*HD];
__device__ __nv_bfloat16 g_Ql[BATCH*NH*SEQ*HD];
__device__ __nv_bfloat16 g_Kh[BATCH*NH*SEQ*HD];
__device__ __nv_bfloat16 g_Kl[BATCH*NH*SEQ*HD];
__device__ __nv_bfloat16 g_Vh[BATCH*NH*SEQ*HD];
__device__ __nv_bfloat16 g_Vl[BATCH*NH*SEQ*HD];

__device__ __nv_bfloat16 s_q [MTOT*KS3];
__device__ __nv_bfloat16 s_k [MTOT*KS3];
__device__ __nv_bfloat16 s_v [MTOT*KS3];
__device__ __nv_bfloat16 s_at[MTOT*KS3];
__device__ __nv_bfloat16 s_wq[HID*KS3];
__device__ __nv_bfloat16 s_wk[HID*KS3];
__device__ __nv_bfloat16 s_wv[HID*KS3];
__device__ __nv_bfloat16 s_wo[HID*KS3];

/* ---------------- helpers ---------------- */
__device__ __forceinline__ uint32_t smem_u32(const void* p) {
    uint32_t a;
    asm("{ .reg .u64 t; cvta.to.shared.u64 t, %1; cvt.u32.u64 %0, t; }"
        : "=r"(a) : "l"(p));
    return a;
}
__device__ __forceinline__ void cp16(uint32_t s, const void* g) {
    asm volatile("cp.async.cg.shared.global [%0], [%1], 16;"
                 :: "r"(s), "l"(g));
}
#define CP_COMMIT() asm volatile("cp.async.commit_group;" ::: "memory")
#define CP_WAIT(N)  asm volatile("cp.async.wait_group %0;" :: "n"(N) : "memory")

__device__ __forceinline__ void ldsm4(uint32_t& r0, uint32_t& r1,
                                      uint32_t& r2, uint32_t& r3, uint32_t addr)
{
    asm volatile("ldmatrix.sync.aligned.m8n8.x4.shared.b16 {%0,%1,%2,%3}, [%4];"
                 : "=r"(r0), "=r"(r1), "=r"(r2), "=r"(r3) : "r"(addr));
}
__device__ __forceinline__ void ldsm4t(uint32_t& r0, uint32_t& r1,
                                       uint32_t& r2, uint32_t& r3, uint32_t addr)
{
    asm volatile("ldmatrix.sync.aligned.m8n8.x4.trans.shared.b16 {%0,%1,%2,%3}, [%4];"
                 : "=r"(r0), "=r"(r1), "=r"(r2), "=r"(r3) : "r"(addr));
}
__device__ __forceinline__ void mma_bf16(float* d, const uint32_t* a,
                                         uint32_t b0, uint32_t b1)
{
    asm volatile(
        "mma.sync.aligned.m16n8k16.row.col.f32.bf16.bf16.f32 "
        "{%0,%1,%2,%3}, {%4,%5,%6,%7}, {%8,%9}, {%0,%1,%2,%3};"
        : "+f"(d[0]), "+f"(d[1]), "+f"(d[2]), "+f"(d[3])
        : "r"(a[0]), "r"(a[1]), "r"(a[2]), "r"(a[3]), "r"(b0), "r"(b1));
}
__device__ __forceinline__ float ex2(float x) {
    float y;
    asm("ex2.approx.ftz.f32 %0, %1;" : "=f"(y) : "f"(x));
    return y;
}
__device__ __forceinline__ uint32_t pack_bf2(float x, float y) {
    __nv_bfloat162 t = __floats2bfloat162_rn(x, y);
    return *(uint32_t*)&t;
}

/* ---------------- RoPE tables ---------------- */
__global__ void rope_table_kernel() {
    int idx = blockIdx.x * blockDim.x + threadIdx.x;
    if (idx >= SEQ * (HD/2)) return;
    int s = idx >> 5;
    int j = idx & 31;
    double inv = exp(-((double)(2*j) / (double)HD) * log(10000.0));
    double ang = (double)s * inv;
    g_cos[idx] = (float)cos(ang);
    g_sin[idx] = (float)sin(ang);
}

/* -------- fp32 -> bf16 splits -------- */
__global__ void __launch_bounds__(256)
split_a_kernel(const float* __restrict__ src, __nv_bfloat16* __restrict__ dst, int n)
{
    int idx = blockIdx.x * blockDim.x + threadIdx.x;
    if (idx >= n) return;
    float x = src[idx];
    int row = idx >> 10, kk = idx & 1023;
    int blk = kk >> 5,  j  = kk & 31;
    __nv_bfloat16 hi = __float2bfloat16(x);
    __nv_bfloat16 lo = __float2bfloat16(x - __bfloat162float(hi));
    size_t base = (size_t)row * KS3 + blk*96 + j;
    dst[base]      = hi;
    dst[base + 32] = lo;
    dst[base + 64] = hi;
}
__global__ void __launch_bounds__(256)
split_b_kernel(const float* __restrict__ src, __nv_bfloat16* __restrict__ dst, int n)
{
    int idx = blockIdx.x * blockDim.x + threadIdx.x;
    if (idx >= n) return;
    float x = src[idx];
    int row = idx >> 10, kk = idx & 1023;
    int blk = kk >> 5,  j  = kk & 31;
    __nv_bfloat16 hi = __float2bfloat16(x);
    __nv_bfloat16 lo = __float2bfloat16(x - __bfloat162float(hi));
    size_t base = (size_t)row * KS3 + blk*96 + j;
    dst[base]      = hi;
    dst[base + 32] = hi;
    dst[base + 64] = lo;
}

/* ================= pipelined mma.sync GEMM =================
   2-stage cp.async. Stage = As(128x72) + Bs(128x72) bf16 = 36864 B. */
#define GSTG 36864

__global__ void __launch_bounds__(256, 2)
gemm_mma(const __nv_bfloat16* __restrict__ A,
         const __nv_bfloat16* __restrict__ B,
         const float* __restrict__ bias,
         float* __restrict__ dst,
         __nv_bfloat16* __restrict__ dhi,
         __nv_bfloat16* __restrict__ dlo, int mode)
{
    extern __shared__ __align__(16) char gsm[];

    const int tid = threadIdx.x;
    const int wid = tid >> 5, l = tid & 31;
    const int warp_m = wid >> 1, warp_n = wid & 1;
    const int m0 = blockIdx.y * 128;
    const int n0 = blockIdx.x * 128;
    const uint32_t sb = smem_u32(gsm);

    const uint4* gA = (const uint4*)(A + (size_t)m0 * KS3);
    const uint4* gB = (const uint4*)(B + (size_t)n0 * KS3);

    float acc[2][8][4];
#pragma unroll
    for (int i = 0; i < 2; i++)
#pragma unroll
        for (int j = 0; j < 8; j++)
#pragma unroll
            for (int p = 0; p < 4; p++) acc[i][j][p] = 0.f;

    /* in-stage ldsm byte offsets */
    uint32_t a_off[2], b_off[4];
#pragma unroll
    for (int mt = 0; mt < 2; mt++)
        a_off[mt] = (warp_m*32 + mt*16 + (l & 15))*144 + (l >> 4)*16;
#pragma unroll
    for (int nt = 0; nt < 4; nt++) {
        int row = warp_n*64 + nt*16 + (l & 7) + ((l >> 4) & 1) * 8;
        b_off[nt] = 18432 + row*144 + ((l >> 3) & 1)*16;
    }

    auto load_stage = [&](int stg, int it) {
        uint32_t base = sb + stg*GSTG;
#pragma unroll
        for (int u = 0; u < 4; u++) {
            int f = u*256 + tid;
            int r = f >> 3, c = f & 7;
            cp16(base + r*144 + c*16,         gA + (size_t)r*(KS3/8) + it*8 + c);
            cp16(base + 18432 + r*144 + c*16, gB + (size_t)r*(KS3/8) + it*8 + c);
        }
    };

    load_stage(0, 0);
    CP_COMMIT();

    for (int it = 0; it < KS3/64; it++) {
        int cur = it & 1;
        if (it + 1 < KS3/64) {
            load_stage(cur ^ 1, it + 1);
            CP_COMMIT();
            CP_WAIT(1);
        } else {
            CP_WAIT(0);
        }
        __syncthreads();

        uint32_t stgb = sb + cur*GSTG;
#pragma unroll
        for (int ks = 0; ks < 4; ks++) {
            uint32_t a[2][4], b[4][4];
#pragma unroll
            for (int mt = 0; mt < 2; mt++)
                ldsm4(a[mt][0], a[mt][1], a[mt][2], a[mt][3],
                      stgb + a_off[mt] + ks*32);
#pragma unroll
            for (int nt = 0; nt < 4; nt++)
                ldsm4(b[nt][0], b[nt][1], b[nt][2], b[nt][3],
                      stgb + b_off[nt] + ks*32);
#pragma unroll
            for (int mt = 0; mt < 2; mt++)
#pragma unroll
                for (int nt = 0; nt < 4; nt++) {
                    mma_bf16(acc[mt][nt*2],   a[mt], b[nt][0], b[nt][1]);
                    mma_bf16(acc[mt][nt*2+1], a[mt], b[nt][2], b[nt][3]);
                }
        }
        __syncthreads();
    }

    /* ---------------- epilogue ---------------- */
    const int g = l >> 2, q = l & 3;
#pragma unroll
    for (int mt = 0; mt < 2; mt++) {
        int mrow0 = m0 + warp_m*32 + mt*16 + g;
#pragma unroll
        for (int nt2 = 0; nt2 < 8; nt2++) {
            int ncol = n0 + warp_n*64 + nt2*8 + q*2;
            float b0 = bias[ncol], b1 = bias[ncol+1];
            float c0 = acc[mt][nt2][0] + b0;
            float c1 = acc[mt][nt2][1] + b1;
            float c2 = acc[mt][nt2][2] + b0;
            float c3 = acc[mt][nt2][3] + b1;

            if (mode == 2) {
                *(float2*)(dst + (size_t)mrow0    *HID + ncol) = make_float2(c0, c1);
                *(float2*)(dst + (size_t)(mrow0+8)*HID + ncol) = make_float2(c2, c3);
            } else {
                int h = ncol >> 6, d = ncol & 63;
                int bb0 = mrow0 >> 11, ss0 = mrow0 & 2047;
                int mrow1 = mrow0 + 8;
                int bb1 = mrow1 >> 11, ss1 = mrow1 & 2047;
                if (mode == 0) {
                    float cs0 = g_cos[ss0*32 + (d>>1)], sn0 = g_sin[ss0*32 + (d>>1)];
                    float cs1 = g_cos[ss1*32 + (d>>1)], sn1 = g_sin[ss1*32 + (d>>1)];
                    float t0 = c0*cs0 - c1*sn0, t1 = c0*sn0 + c1*cs0;
                    float t2 = c2*cs1 - c3*sn1, t3 = c2*sn1 + c3*cs1;
                    c0 = t0; c1 = t1; c2 = t2; c3 = t3;
                }
                size_t a0 = (((size_t)(bb0*NH + h)*SEQ + ss0) << 6) + d;
                size_t a1 = (((size_t)(bb1*NH + h)*SEQ + ss1) << 6) + d;
                __nv_bfloat16 h0 = __float2bfloat16(c0);
                __nv_bfloat16 h1 = __float2bfloat16(c1);
                __nv_bfloat16 h2 = __float2bfloat16(c2);
                __nv_bfloat16 h3 = __float2bfloat16(c3);
                *(__nv_bfloat162*)(dhi + a0) = __halves2bfloat162(h0, h1);
                *(__nv_bfloat162*)(dhi + a1) = __halves2bfloat162(h2, h3);
                *(__nv_bfloat162*)(dlo + a0) = __floats2bfloat162_rn(
                    c0 - __bfloat162float(h0), c1 - __bfloat162float(h1));
                *(__nv_bfloat162*)(dlo + a1) = __floats2bfloat162_rn(
                    c2 - __bfloat162float(h2), c3 - __bfloat162float(h3));
            }
        }
    }
}

/* ================= pipelined attention =================
   smem: Q (hi 18432 + lo 18432) resident; 2 K/V stages of 36864 B:
   in-stage: KH 0, KL 9216, VH 18432, VL 27648.
   Total dynamic smem = 110592 B -> 2 CTAs/SM.                        */
#define QSZ   36864
#define ASTG  36864
#define ASMEM (QSZ + 2*ASTG)

__global__ void __launch_bounds__(256, 2)
attn_mma(float* __restrict__ wout, int write_w)
{
    extern __shared__ __align__(16) char dsm[];
    const int tid = threadIdx.x;
    const int w = tid >> 5, l = tid & 31;
    const int g = l >> 2, q = l & 3;
    const int qt = (gridDim.x - 1) - blockIdx.x;    /* heavy tiles first */
    const int h = blockIdx.y, b = blockIdx.z;
    const int q0 = qt * 128;
    const size_t basebh = (size_t)(b*NH + h) * SEQ;
    const uint32_t sb = smem_u32(dsm);

    /* Q loads (group 0) */
    {
        const uint4* gh = (const uint4*)(g_Qh + (basebh + q0) * HD);
        const uint4* gl = (const uint4*)(g_Ql + (basebh + q0) * HD);
#pragma unroll
        for (int u = 0; u < 4; u++) {
            int f = u*256 + tid;
            int r = f >> 3, c = f & 7;
            cp16(sb + r*144 + c*16,         gh + r*8 + c);
            cp16(sb + 18432 + r*144 + c*16, gl + r*8 + c);
        }
        CP_COMMIT();
    }

    const uint32_t aQh = sb + (w*16 + (l & 15))*144 + (l >> 4)*16;
    const uint32_t aQl = aQh + 18432;
    uint32_t bk_off[4];
    {
        int krow = (l & 7) + ((l >> 4) & 1) * 8;
        int kcb  = ((l >> 3) & 1) * 16;
#pragma unroll
        for (int nt = 0; nt < 4; nt++)
            bk_off[nt] = (nt*16 + krow)*144 + kcb;
    }
    const uint32_t av_off = 18432 + (l & 15)*144 + (l >> 4)*16;

    const float CE = 0.125f * LOG2E;
    const int nkt = 2*qt + 2;
    const int rw0 = q0 + w*16;
    const int r0 = rw0 + g, r1 = r0 + 8;

    auto loadK = [&](int stg, int kb) {
        uint32_t base = sb + QSZ + stg*ASTG;
        const uint4* gkh = (const uint4*)(g_Kh + (basebh + kb*64) * HD);
        const uint4* gkl = (const uint4*)(g_Kl + (basebh + kb*64) * HD);
#pragma unroll
        for (int u = 0; u < 2; u++) {
            int f = u*256 + tid;
            int r = f >> 3, c = f & 7;
            cp16(base + r*144 + c*16,        gkh + r*8 + c);
            cp16(base + 9216 + r*144 + c*16, gkl + r*8 + c);
        }
    };
    auto loadKV = [&](int stg, int kb) {
        uint32_t base = sb + QSZ + stg*ASTG;
        const uint4* gkh = (const uint4*)(g_Kh + (basebh + kb*64) * HD);
        const uint4* gkl = (const uint4*)(g_Kl + (basebh + kb*64) * HD);
        const uint4* gvh = (const uint4*)(g_Vh + (basebh + kb*64) * HD);
        const uint4* gvl = (const uint4*)(g_Vl + (basebh + kb*64) * HD);
#pragma unroll
        for (int u = 0; u < 2; u++) {
            int f = u*256 + tid;
            int r = f >> 3, c = f & 7;
            cp16(base + r*144 + c*16,         gkh + r*8 + c);
            cp16(base + 9216  + r*144 + c*16, gkl + r*8 + c);
            cp16(base + 18432 + r*144 + c*16, gvh + r*8 + c);
            cp16(base + 27648 + r*144 + c*16, gvl + r*8 + c);
        }
    };

    float m2[2] = {-1e30f, -1e30f};
    float l2[2] = {0.f, 0.f};

    /* ---------------- PASS 1 ---------------- */
    loadK(0, 0);
    CP_COMMIT();

    for (int kb = 0; kb < nkt; kb++) {
        int cur = kb & 1;
        if (kb + 1 < nkt) {
            loadK(cur ^ 1, kb + 1);
            CP_COMMIT();
            CP_WAIT(1);
        } else {
            CP_WAIT(0);
        }
        __syncthreads();

        uint32_t kbase = sb + QSZ + cur*ASTG;

        float acc[8][4];
#pragma unroll
        for (int nt = 0; nt < 8; nt++)
#pragma unroll
            for (int p = 0; p < 4; p++) acc[nt][p] = 0.f;

#pragma unroll
        for (int ks = 0; ks < 4; ks++) {
            uint32_t ah[4], al[4];
            ldsm4(ah[0], ah[1], ah[2], ah[3], aQh + ks*32);
            ldsm4(al[0], al[1], al[2], al[3], aQl + ks*32);
#pragma unroll
            for (int np = 0; np < 4; np++) {
                uint32_t kh[4], kl[4];
                ldsm4(kh[0], kh[1], kh[2], kh[3], kbase + bk_off[np] + ks*32);
                ldsm4(kl[0], kl[1], kl[2], kl[3], kbase + 9216 + bk_off[np] + ks*32);
                mma_bf16(acc[np*2],   ah, kh[0], kh[1]);
                mma_bf16(acc[np*2+1], ah, kh[2], kh[3]);
                mma_bf16(acc[np*2],   al, kh[0], kh[1]);
                mma_bf16(acc[np*2+1], al, kh[2], kh[3]);
                mma_bf16(acc[np*2],   ah, kl[0], kl[1]);
                mma_bf16(acc[np*2+1], ah, kl[2], kl[3]);
            }
        }
        __syncthreads();

        const bool needmask = (kb*64 + 63) > rw0;
#pragma unroll
        for (int nt = 0; nt < 8; nt++) {
            int k0c = kb*64 + nt*8 + q*2;
            acc[nt][0] = (!needmask || k0c   <= r0) ? acc[nt][0]*CE : -1e30f;
            acc[nt][1] = (!needmask || k0c+1 <= r0) ? acc[nt][1]*CE : -1e30f;
            acc[nt][2] = (!needmask || k0c   <= r1) ? acc[nt][2]*CE : -1e30f;
            acc[nt][3] = (!needmask || k0c+1 <= r1) ? acc[nt][3]*CE : -1e30f;
        }
        float tm0 = -1e30f, tm1 = -1e30f;
#pragma unroll
        for (int nt = 0; nt < 8; nt++) {
            tm0 = fmaxf(tm0, fmaxf(acc[nt][0], acc[nt][1]));
            tm1 = fmaxf(tm1, fmaxf(acc[nt][2], acc[nt][3]));
        }
        tm0 = fmaxf(tm0, __shfl_xor_sync(0xffffffffu, tm0, 1));
        tm0 = fmaxf(tm0, __shfl_xor_sync(0xffffffffu, tm0, 2));
        tm1 = fmaxf(tm1, __shfl_xor_sync(0xffffffffu, tm1, 1));
        tm1 = fmaxf(tm1, __shfl_xor_sync(0xffffffffu, tm1, 2));
        float mn0 = fmaxf(m2[0], tm0), mn1 = fmaxf(m2[1], tm1);
        float s0 = 0.f, s1 = 0.f;
#pragma unroll
        for (int nt = 0; nt < 8; nt++) {
            s0 += ex2(acc[nt][0] - mn0) + ex2(acc[nt][1] - mn0);
            s1 += ex2(acc[nt][2] - mn1) + ex2(acc[nt][3] - mn1);
        }
        s0 += __shfl_xor_sync(0xffffffffu, s0, 1);
        s0 += __shfl_xor_sync(0xffffffffu, s0, 2);
        s1 += __shfl_xor_sync(0xffffffffu, s1, 1);
        s1 += __shfl_xor_sync(0xffffffffu, s1, 2);
        l2[0] = l2[0] * ex2(m2[0] - mn0) + s0;  m2[0] = mn0;
        l2[1] = l2[1] * ex2(m2[1] - mn1) + s1;  m2[1] = mn1;
    }

    const float invl0 = 1.f / l2[0];
    const float invl1 = 1.f / l2[1];

    float o[8][4];
#pragma unroll
    for (int nd = 0; nd < 8; nd++)
#pragma unroll
        for (int p = 0; p < 4; p++) o[nd][p] = 0.f;

    /* ---------------- PASS 2 ---------------- */
    loadKV(0, 0);
    CP_COMMIT();

    for (int kb = 0; kb < nkt; kb++) {
        int cur = kb & 1;
        if (kb + 1 < nkt) {
            loadKV(cur ^ 1, kb + 1);
            CP_COMMIT();
            CP_WAIT(1);
        } else {
            CP_WAIT(0);
        }
        __syncthreads();

        uint32_t kbase = sb + QSZ + cur*ASTG;

        float acc[8][4];
#pragma unroll
        for (int nt = 0; nt < 8; nt++)
#pragma unroll
            for (int p = 0; p < 4; p++) acc[nt][p] = 0.f;

#pragma unroll
        for (int ks = 0; ks < 4; ks++) {
            uint32_t ah[4], al[4];
            ldsm4(ah[0], ah[1], ah[2], ah[3], aQh + ks*32);
            ldsm4(al[0], al[1], al[2], al[3], aQl + ks*32);
#pragma unroll
            for (int np = 0; np < 4; np++) {
                uint32_t kh[4], kl[4];
                ldsm4(kh[0], kh[1], kh[2], kh[3], kbase + bk_off[np] + ks*32);
                ldsm4(kl[0], kl[1], kl[2], kl[3], kbase + 9216 + bk_off[np] + ks*32);
                mma_bf16(acc[np*2],   ah, kh[0], kh[1]);
                mma_bf16(acc[np*2+1], ah, kh[2], kh[3]);
                mma_bf16(acc[np*2],   al, kh[0], kh[1]);
                mma_bf16(acc[np*2+1], al, kh[2], kh[3]);
                mma_bf16(acc[np*2],   ah, kl[0], kl[1]);
                mma_bf16(acc[np*2+1], ah, kl[2], kl[3]);
            }
        }

        const bool needmask = (kb*64 + 63) > rw0;
#pragma unroll
        for (int nt = 0; nt < 8; nt++) {
            int k0c = kb*64 + nt*8 + q*2;
            float w0 = (!needmask || k0c   <= r0)
                       ? ex2(acc[nt][0]*CE - m2[0]) * invl0 : 0.f;
            float w1 = (!needmask || k0c+1 <= r0)
                       ? ex2(acc[nt][1]*CE - m2[0]) * invl0 : 0.f;
            float w2 = (!needmask || k0c   <= r1)
                       ? ex2(acc[nt][2]*CE - m2[1]) * invl1 : 0.f;
            float w3 = (!needmask || k0c+1 <= r1)
                       ? ex2(acc[nt][3]*CE - m2[1]) * invl1 : 0.f;
            acc[nt][0] = w0; acc[nt][1] = w1; acc[nt][2] = w2; acc[nt][3] = w3;
            if (write_w) {
                __stcs((float2*)(wout + (basebh + r0)*SEQ + k0c), make_float2(w0, w1));
                __stcs((float2*)(wout + (basebh + r1)*SEQ + k0c), make_float2(w2, w3));
            }
        }

        /* PV: W fragments straight from acc */
#pragma unroll
        for (int t = 0; t < 4; t++) {
            uint32_t awh[4], awl[4];
            {
                float c0 = acc[2*t][0],   c1 = acc[2*t][1];
                float c2 = acc[2*t][2],   c3 = acc[2*t][3];
                float d0 = acc[2*t+1][0], d1 = acc[2*t+1][1];
                float d2 = acc[2*t+1][2], d3 = acc[2*t+1][3];
                awh[0] = pack_bf2(c0, c1);
                awh[1] = pack_bf2(c2, c3);
                awh[2] = pack_bf2(d0, d1);
                awh[3] = pack_bf2(d2, d3);
                __nv_bfloat162* ph;
                ph = (__nv_bfloat162*)&awh[0];
                awl[0] = pack_bf2(c0 - __bfloat162float(ph->x),
                                  c1 - __bfloat162float(ph->y));
                ph = (__nv_bfloat162*)&awh[1];
                awl[1] = pack_bf2(c2 - __bfloat162float(ph->x),
                                  c3 - __bfloat162float(ph->y));
                ph = (__nv_bfloat162*)&awh[2];
                awl[2] = pack_bf2(d0 - __bfloat162float(ph->x),
                                  d1 - __bfloat162float(ph->y));
                ph = (__nv_bfloat162*)&awh[3];
                awl[3] = pack_bf2(d2 - __bfloat162float(ph->x),
                                  d3 - __bfloat162float(ph->y));
            }
#pragma unroll
            for (int nd = 0; nd < 4; nd++) {
                uint32_t vh[4], vl[4];
                ldsm4t(vh[0], vh[1], vh[2], vh[3],
                       kbase + av_off + t*2304 + nd*32);
                ldsm4t(vl[0], vl[1], vl[2], vl[3],
                       kbase + av_off + 9216 + t*2304 + nd*32);
                mma_bf16(o[nd*2],   awh, vh[0], vh[1]);
                mma_bf16(o[nd*2+1], awh, vh[2], vh[3]);
                mma_bf16(o[nd*2],   awl, vh[0], vh[1]);
                mma_bf16(o[nd*2+1], awl, vh[2], vh[3]);
                mma_bf16(o[nd*2],   awh, vl[0], vl[1]);
                mma_bf16(o[nd*2+1], awh, vl[2], vl[3]);
            }
        }
        __syncthreads();
    }

    /* zero-fill masked (upper-triangle) region */
    if (write_w) {
        int kend = q0 + 128;
        int rem = SEQ - kend;
        if (rem > 0) {
            float4 z4 = make_float4(0.f, 0.f, 0.f, 0.f);
            for (int r = tid >> 5; r < 128; r += 8) {
                float* rowp = wout + (basebh + q0 + r)*SEQ + kend;
                for (int cc = (tid & 31)*4; cc < rem; cc += 128)
                    __stcs((float4*)(rowp + cc), z4);
            }
        }
    }

    /* write O in split-A format */
    {
        size_t mg0 = (size_t)b*SEQ + q0 + w*16 + g;
        size_t mg1 = mg0 + 8;
#pragma unroll
        for (int nd = 0; nd < 8; nd++) {
            int col = h*64 + nd*8 + q*2;
            int blk = col >> 5, j = col & 31;
            size_t b0 = mg0*KS3 + blk*96 + j;
            size_t b1 = mg1*KS3 + blk*96 + j;
            float c0 = o[nd][0], c1 = o[nd][1];
            float c2 = o[nd][2], c3 = o[nd][3];
            __nv_bfloat16 h0 = __float2bfloat16(c0);
            __nv_bfloat16 h1 = __float2bfloat16(c1);
            __nv_bfloat16 h2 = __float2bfloat16(c2);
            __nv_bfloat16 h3 = __float2bfloat16(c3);
            __nv_bfloat162 hi0 = __halves2bfloat162(h0, h1);
            __nv_bfloat162 hi1 = __halves2bfloat162(h2, h3);
            __nv_bfloat162 lo0 = __floats2bfloat162_rn(
                c0 - __bfloat162float(h0), c1 - __bfloat162float(h1));
            __nv_bfloat162 lo1 = __floats2bfloat162_rn(
                c2 - __bfloat162float(h2), c3 - __bfloat162float(h3));
            *(__nv_bfloat162*)(s_at + b0)      = hi0;
            *(__nv_bfloat162*)(s_at + b0 + 32) = lo0;
            *(__nv_bfloat162*)(s_at + b0 + 64) = hi0;
            *(__nv_bfloat162*)(s_at + b1)      = hi1;
            *(__nv_bfloat162*)(s_at + b1 + 32) = lo1;
            *(__nv_bfloat162*)(s_at + b1 + 64) = hi1;
        }
    }
}

/* ---------------- launcher ---------------- */
extern "C" void kernel_launch(void* const* d_in, const int* in_sizes, int n_in,
                              void* d_out, int out_size)
{
    const float* q  = (const float*)d_in[0];
    const float* k  = (const float*)d_in[1];
    const float* v  = (const float*)d_in[2];
    const float* Wq = (const float*)d_in[3];
    const float* bq = (const float*)d_in[4];
    const float* Wk = (const float*)d_in[5];
    const float* bk = (const float*)d_in[6];
    const float* Wv = (const float*)d_in[7];
    const float* bv = (const float*)d_in[8];
    const float* Wo = (const float*)d_in[9];
    const float* bo = (const float*)d_in[10];

    float* out  = (float*)d_out;
    int write_w = (out_size >= OUT_ELEMS + W_ELEMS) ? 1 : 0;
    float* wout = out + OUT_ELEMS;

    __nv_bfloat16 *p_sq, *p_sk, *p_sv, *p_swq, *p_swk, *p_swv, *p_swo, *p_sat;
    __nv_bfloat16 *p_qh, *p_ql, *p_kh, *p_kl, *p_vh, *p_vl;
    cudaGetSymbolAddress((void**)&p_sq,  s_q);
    cudaGetSymbolAddress((void**)&p_sk,  s_k);
    cudaGetSymbolAddress((void**)&p_sv,  s_v);
    cudaGetSymbolAddress((void**)&p_swq, s_wq);
    cudaGetSymbolAddress((void**)&p_swk, s_wk);
    cudaGetSymbolAddress((void**)&p_swv, s_wv);
    cudaGetSymbolAddress((void**)&p_swo, s_wo);
    cudaGetSymbolAddress((void**)&p_sat, s_at);
    cudaGetSymbolAddress((void**)&p_qh, g_Qh);
    cudaGetSymbolAddress((void**)&p_ql, g_Ql);
    cudaGetSymbolAddress((void**)&p_kh, g_Kh);
    cudaGetSymbolAddress((void**)&p_kl, g_Kl);
    cudaGetSymbolAddress((void**)&p_vh, g_Vh);
    cudaGetSymbolAddress((void**)&p_vl, g_Vl);

    rope_table_kernel<<<(SEQ*32 + 255)/256, 256>>>();

    const int nIn = MTOT * HID;
    const int nW  = HID * HID;
    split_a_kernel<<<(nIn+255)/256, 256>>>(q,  p_sq,  nIn);
    split_a_kernel<<<(nIn+255)/256, 256>>>(k,  p_sk,  nIn);
    split_a_kernel<<<(nIn+255)/256, 256>>>(v,  p_sv,  nIn);
    split_b_kernel<<<(nW +255)/256, 256>>>(Wq, p_swq, nW);
    split_b_kernel<<<(nW +255)/256, 256>>>(Wk, p_swk, nW);
    split_b_kernel<<<(nW +255)/256, 256>>>(Wv, p_swv, nW);
    split_b_kernel<<<(nW +255)/256, 256>>>(Wo, p_swo, nW);

    cudaFuncSetAttribute(gemm_mma,
                         cudaFuncAttributeMaxDynamicSharedMemorySize, 2*GSTG);
    cudaFuncSetAttribute(attn_mma,
                         cudaFuncAttributeMaxDynamicSharedMemorySize, ASMEM);

    dim3 ggrid(HID/128, MTOT/128);   /* (8, 32) */
    gemm_mma<<<ggrid, 256, 2*GSTG>>>(p_sq, p_swq, bq, nullptr, p_qh, p_ql, 0);
    gemm_mma<<<ggrid, 256, 2*GSTG>>>(p_sk, p_swk, bk, nullptr, p_kh, p_kl, 0);
    gemm_mma<<<ggrid, 256, 2*GSTG>>>(p_sv, p_swv, bv, nullptr, p_vh, p_vl, 1);

    attn_mma<<<dim3(SEQ/128, NH, BATCH), 256, ASMEM>>>(wout, write_w);

    gemm_mma<<<ggrid, 256, 2*GSTG>>>(p_sat, p_swo, bo, out, nullptr, nullptr, 2);
}